// round 10
// baseline (speedup 1.0000x reference)
#include <cuda_runtime.h>

#define NN 50000
#define EE 800000
#define HH 64
#define D0 128
#define DE 32
#define NEG 0.2f

typedef unsigned long long ull;

// ---------------- scratch (static device globals; no allocation) ----------------
__device__ __align__(16) float g_h  [NN * HH];
__device__ __align__(16) float g_x1 [NN * HH];
__device__ __align__(16) float g_x2 [NN * HH];
__device__ __align__(16) float g_u  [NN * HH];
__device__ __align__(16) float g_v  [NN * HH];
__device__ float g_ssrc[NN], g_sdst[NN];
__device__ int   g_degi[NN];
__device__ int   g_rowptr[NN + 1];
__device__ int   g_cnt[NN];
__device__ int   g_bsum[128];
__device__ __align__(16) float4 g_csr[EE];   // {src_bits, t1, t2, pad} per edge, CSR by dst
__device__ float g_wv1[DE], g_wv2[DE];

__device__ __forceinline__ float lrelu(float z) { return z >= 0.f ? z : NEG * z; }

// ---- packed f32x2 helpers ----
__device__ __forceinline__ ull pk2(float x, float y) {
    ull r; asm("mov.b64 %0, {%1,%2};" : "=l"(r) : "f"(x), "f"(y)); return r;
}
__device__ __forceinline__ void fma2(ull& d, ull a, ull b) {
    asm("fma.rn.f32x2 %0, %1, %2, %0;" : "+l"(d) : "l"(a), "l"(b));
}
__device__ __forceinline__ ull add2(ull a, ull b) {
    ull r; asm("add.rn.f32x2 %0, %1, %2;" : "=l"(r) : "l"(a), "l"(b)); return r;
}
__device__ __forceinline__ float2 upk2(ull v) {
    float2 f; asm("mov.b64 {%0,%1}, %2;" : "=f"(f.x), "=f"(f.y) : "l"(v)); return f;
}
__device__ __forceinline__ float hsum2(ull v) {
    float2 f = upk2(v); return f.x + f.y;
}

// ---------------- zero counters + prep wv = We @ a_edge ----------------
__global__ void k_zero_prep(const float* __restrict__ We1, const float* __restrict__ ae1,
                            const float* __restrict__ We2, const float* __restrict__ ae2) {
    int i = blockIdx.x * blockDim.x + threadIdx.x;
    if (i < NN) { g_degi[i] = 0; g_cnt[i] = 0; }
    if (i == 0) g_rowptr[NN] = EE;
    if (blockIdx.x == 0 && threadIdx.x >= 32 && threadIdx.x < 64) {
        int k = threadIdx.x - 32;
        float s1 = 0.f, s2 = 0.f;
        #pragma unroll 8
        for (int j = 0; j < HH; j++) {
            s1 = fmaf(We1[k * HH + j], ae1[j], s1);
            s2 = fmaf(We2[k * HH + j], ae2[j], s2);
        }
        g_wv1[k] = s1;
        g_wv2[k] = s2;
    }
}

// degree histogram (dst only)
__global__ void __launch_bounds__(256) k_hist(const int* __restrict__ dst) {
    int e = blockIdx.x * 256 + threadIdx.x;   // grid exactly EE/256
    atomicAdd(&g_degi[dst[e]], 1);
}

// ---------------- parallel scan: degi -> rowptr ----------------
#define SCAN_B 512
#define SCAN_G 98          // 98*512 = 50176 >= NN

__global__ void __launch_bounds__(SCAN_B) k_scanA() {
    __shared__ int ws[SCAN_B / 32];
    int idx = blockIdx.x * SCAN_B + threadIdx.x;
    int v = (idx < NN) ? g_degi[idx] : 0;
    int s = v;
    #pragma unroll
    for (int o = 16; o > 0; o >>= 1) s += __shfl_xor_sync(0xffffffffu, s, o);
    if ((threadIdx.x & 31) == 0) ws[threadIdx.x >> 5] = s;
    __syncthreads();
    if (threadIdx.x < SCAN_B / 32) {
        int t = ws[threadIdx.x];
        #pragma unroll
        for (int o = 8; o > 0; o >>= 1) t += __shfl_xor_sync(0xffffu, t, o);
        if (threadIdx.x == 0) g_bsum[blockIdx.x] = t;
    }
}

__global__ void __launch_bounds__(SCAN_B) k_scanC() {
    __shared__ int wsum[4];
    __shared__ int ws[SCAN_B / 32];
    __shared__ int spre;
    int tid = threadIdx.x, lane = tid & 31, w = tid >> 5;
    if (tid < 128) {
        int pv = (tid < blockIdx.x) ? g_bsum[tid] : 0;
        #pragma unroll
        for (int o = 16; o > 0; o >>= 1) pv += __shfl_xor_sync(0xffffffffu, pv, o);
        if (lane == 0) wsum[w] = pv;
    }
    int idx = blockIdx.x * SCAN_B + tid;
    int v = (idx < NN) ? g_degi[idx] : 0;
    int inc = v;
    #pragma unroll
    for (int o = 1; o < 32; o <<= 1) {
        int x = __shfl_up_sync(0xffffffffu, inc, o);
        if (lane >= o) inc += x;
    }
    if (lane == 31) ws[w] = inc;
    __syncthreads();
    if (tid == 0) spre = wsum[0] + wsum[1] + wsum[2] + wsum[3];
    if (w == 0 && lane < SCAN_B / 32) {
        int y = ws[lane];
        #pragma unroll
        for (int o = 1; o < SCAN_B / 32; o <<= 1) {
            int x = __shfl_up_sync(0xffffu, y, o);
            if (lane >= o) y += x;
        }
        ws[lane] = y;
    }
    __syncthreads();
    int off = inc - v + (w > 0 ? ws[w - 1] : 0) + spre;
    if (idx < NN) g_rowptr[idx] = off;
}

// fused: compute t1/t2 from ea, scatter packed 16B CSR record
__global__ void __launch_bounds__(256) k_scatter_t(const float* __restrict__ ea,
                                                   const int* __restrict__ src,
                                                   const int* __restrict__ dst) {
    __shared__ float wv1s[DE], wv2s[DE];
    int tid = threadIdx.x;
    if (tid < DE) { wv1s[tid] = g_wv1[tid]; wv2s[tid] = g_wv2[tid]; }
    __syncthreads();
    int e = blockIdx.x * 256 + tid;           // grid exactly EE/256
    const float4* p = (const float4*)(ea + (size_t)e * DE);
    float t1 = 0.f, t2 = 0.f;
    #pragma unroll
    for (int q = 0; q < 8; q++) {
        float4 v = p[q];
        t1 = fmaf(v.x, wv1s[4*q+0], t1); t1 = fmaf(v.y, wv1s[4*q+1], t1);
        t1 = fmaf(v.z, wv1s[4*q+2], t1); t1 = fmaf(v.w, wv1s[4*q+3], t1);
        t2 = fmaf(v.x, wv2s[4*q+0], t2); t2 = fmaf(v.y, wv2s[4*q+1], t2);
        t2 = fmaf(v.z, wv2s[4*q+2], t2); t2 = fmaf(v.w, wv2s[4*q+3], t2);
    }
    int d = dst[e];
    int pos = g_rowptr[d] + atomicAdd(&g_cnt[d], 1);
    g_csr[pos] = make_float4(__int_as_float(src[e]), t1, t2, 0.f);
}

// ---------------- GEMM: 64x64 tile, thread = 4 rows x 4 cols, packed-k FFMA2 ----------------
// dynamic smem: Wp[(DIN/2)*64] ull, then Xs[64*DIN] float
template <int DIN, int SRC>
__global__ void __launch_bounds__(256, 2) k_gemm(const float* __restrict__ xin_p,
                                                 const float* __restrict__ W,
                                                 const float* __restrict__ as,
                                                 const float* __restrict__ ad) {
    extern __shared__ char sm[];
    ull*   Wp = (ull*)sm;                              // (DIN/2) * 64
    float* Xs = (float*)(sm + (DIN / 2) * 64 * 8);     // 64 * DIN
    const float* xin = SRC ? g_x1 : xin_p;
    int tid = threadIdx.x;

    for (int i = tid; i < (DIN / 2) * 64; i += 256) {
        int k2 = i >> 6, c = i & 63;
        Wp[i] = pk2(W[(2 * k2) * HH + c], W[(2 * k2 + 1) * HH + c]);
    }
    int r0g = blockIdx.x * 64;                         // grid = ceil(NN/64)
    for (int i = tid; i < 64 * DIN / 4; i += 256) {
        int r = i / (DIN / 4), q = i % (DIN / 4);
        float4 vv = (r0g + r < NN) ? ((const float4*)(xin + (size_t)(r0g + r) * DIN))[q]
                                   : make_float4(0.f, 0.f, 0.f, 0.f);
        ((float4*)Xs)[i] = vv;
    }
    __syncthreads();

    int tx = tid & 15, ty = tid >> 4;                  // cols 4tx..4tx+3, rows 4ty..4ty+3
    const ull* X0 = (const ull*)(Xs + (4 * ty + 0) * DIN);
    const ull* X1 = (const ull*)(Xs + (4 * ty + 1) * DIN);
    const ull* X2 = (const ull*)(Xs + (4 * ty + 2) * DIN);
    const ull* X3 = (const ull*)(Xs + (4 * ty + 3) * DIN);

    ull a00=0,a01=0,a02=0,a03=0, a10=0,a11=0,a12=0,a13=0;
    ull a20=0,a21=0,a22=0,a23=0, a30=0,a31=0,a32=0,a33=0;
    #pragma unroll 8
    for (int k2 = 0; k2 < DIN / 2; k2++) {
        ull x0 = X0[k2], x1 = X1[k2], x2 = X2[k2], x3 = X3[k2];
        ulonglong2 wA = ((const ulonglong2*)(Wp + k2 * 64 + 4 * tx))[0];
        ulonglong2 wB = ((const ulonglong2*)(Wp + k2 * 64 + 4 * tx))[1];
        fma2(a00, x0, wA.x); fma2(a01, x0, wA.y); fma2(a02, x0, wB.x); fma2(a03, x0, wB.y);
        fma2(a10, x1, wA.x); fma2(a11, x1, wA.y); fma2(a12, x1, wB.x); fma2(a13, x1, wB.y);
        fma2(a20, x2, wA.x); fma2(a21, x2, wA.y); fma2(a22, x2, wB.x); fma2(a23, x2, wB.y);
        fma2(a30, x3, wA.x); fma2(a31, x3, wA.y); fma2(a32, x3, wB.x); fma2(a33, x3, wB.y);
    }

    float4 res[4];
    res[0] = make_float4(hsum2(a00), hsum2(a01), hsum2(a02), hsum2(a03));
    res[1] = make_float4(hsum2(a10), hsum2(a11), hsum2(a12), hsum2(a13));
    res[2] = make_float4(hsum2(a20), hsum2(a21), hsum2(a22), hsum2(a23));
    res[3] = make_float4(hsum2(a30), hsum2(a31), hsum2(a32), hsum2(a33));

    float4 as4 = ((const float4*)as)[tx];
    float4 ad4 = ((const float4*)ad)[tx];
    float ps[4], pd[4];
    #pragma unroll
    for (int i = 0; i < 4; i++) {
        int gr = r0g + 4 * ty + i;
        if (gr < NN) ((float4*)(g_h + (size_t)gr * HH))[tx] = res[i];
        ps[i] = res[i].x*as4.x + res[i].y*as4.y + res[i].z*as4.z + res[i].w*as4.w;
        pd[i] = res[i].x*ad4.x + res[i].y*ad4.y + res[i].z*ad4.z + res[i].w*ad4.w;
    }
    #pragma unroll
    for (int o = 8; o > 0; o >>= 1) {
        #pragma unroll
        for (int i = 0; i < 4; i++) {
            ps[i] += __shfl_xor_sync(0xffffffffu, ps[i], o);
            pd[i] += __shfl_xor_sync(0xffffffffu, pd[i], o);
        }
    }
    if (tx == 0) {
        #pragma unroll
        for (int i = 0; i < 4; i++) {
            int gr = r0g + 4 * ty + i;
            if (gr < NN) { g_ssrc[gr] = ps[i]; g_sdst[gr] = pd[i]; }
        }
    }
}

// single-pass per-dst softmax + aggregation, packed CSR records (R5-proven loop)
template <int LAYER>
__global__ void __launch_bounds__(256) k_attn(const float* __restrict__ b) {
    int lane = threadIdx.x & 31;
    int n = blockIdx.x * 8 + (threadIdx.x >> 5);   // grid exactly NN/8
    float* xout = LAYER ? g_x2 : g_x1;
    int beg = g_rowptr[n], end = g_rowptr[n + 1];
    float sd = g_sdst[n], ss = g_ssrc[n];

    const ull* h2 = (const ull*)g_h;
    ull acc2 = 0;
    float ssum = 0.f, tsum = 0.f;
    for (int base = beg; base < end; base += 32) {
        int j = base + lane;
        float ev = 0.f; int si = 0;
        if (j < end) {
            float4 rec = g_csr[j];
            si = __float_as_int(rec.x);
            float t = LAYER ? rec.z : rec.y;
            ev = __expf(lrelu(g_ssrc[si] + sd + t));
            tsum += t;
        }
        ssum += ev;
        int cnt = min(32, end - base);
        #pragma unroll 4
        for (int k = 0; k < cnt; k++) {
            int   s = __shfl_sync(0xffffffffu, si, k);
            float w = __shfl_sync(0xffffffffu, ev, k);
            fma2(acc2, pk2(w, w), h2[(size_t)s * 32 + lane]);
        }
    }
    #pragma unroll
    for (int o = 16; o > 0; o >>= 1) {
        ssum += __shfl_xor_sync(0xffffffffu, ssum, o);
        tsum += __shfl_xor_sync(0xffffffffu, tsum, o);
    }

    float deg = (float)(end - beg);
    float tl = tsum / fmaxf(deg, 1.0f);
    float eself = __expf(lrelu(ss + sd + tl));
    float inv = 1.f / (ssum + eself);
    float aself = eself * inv;

    float2 a = upk2(acc2);
    float2 hn = upk2(h2[(size_t)n * 32 + lane]);
    float2 bv = ((const float2*)b)[lane];
    float2 o2;
    o2.x = fmaxf(fmaf(a.x, inv, fmaf(aself, hn.x, bv.x)), 0.f);
    o2.y = fmaxf(fmaf(a.y, inv, fmaf(aself, hn.y, bv.y)), 0.f);
    ((float2*)xout)[(size_t)n * 32 + lane] = o2;
}

// ---------------- classifier ----------------
// u = x2 @ Wc1[0:64], v = x2 @ Wc1[64:128]  — 64x64 tile, 4 rows x 4 cols per thread
__global__ void __launch_bounds__(256, 2) k_gemm_uv(const float* __restrict__ Wc1) {
    __shared__ ull Wu[(HH / 2) * HH];     // 16 KB
    __shared__ ull Wv[(HH / 2) * HH];     // 16 KB
    __shared__ float Xs[64 * HH];         // 16 KB
    int tid = threadIdx.x;
    for (int i = tid; i < (HH / 2) * HH; i += 256) {
        int k2 = i >> 6, c = i & 63;
        Wu[i] = pk2(Wc1[(2 * k2) * HH + c], Wc1[(2 * k2 + 1) * HH + c]);
        Wv[i] = pk2(Wc1[(HH + 2 * k2) * HH + c], Wc1[(HH + 2 * k2 + 1) * HH + c]);
    }
    int r0g = blockIdx.x * 64;                        // grid = ceil(NN/64)
    for (int i = tid; i < 64 * HH / 4; i += 256) {
        int r = i / (HH / 4), q = i % (HH / 4);
        float4 vv = (r0g + r < NN) ? ((const float4*)(g_x2 + (size_t)(r0g + r) * HH))[q]
                                   : make_float4(0.f, 0.f, 0.f, 0.f);
        ((float4*)Xs)[i] = vv;
    }
    __syncthreads();

    int tx = tid & 15, ty = tid >> 4;
    const ull* X0 = (const ull*)(Xs + (4 * ty + 0) * HH);
    const ull* X1 = (const ull*)(Xs + (4 * ty + 1) * HH);
    const ull* X2 = (const ull*)(Xs + (4 * ty + 2) * HH);
    const ull* X3 = (const ull*)(Xs + (4 * ty + 3) * HH);

    ull u00=0,u01=0,u02=0,u03=0, u10=0,u11=0,u12=0,u13=0;
    ull u20=0,u21=0,u22=0,u23=0, u30=0,u31=0,u32=0,u33=0;
    ull v00=0,v01=0,v02=0,v03=0, v10=0,v11=0,v12=0,v13=0;
    ull v20=0,v21=0,v22=0,v23=0, v30=0,v31=0,v32=0,v33=0;
    #pragma unroll 4
    for (int k2 = 0; k2 < HH / 2; k2++) {
        ull x0 = X0[k2], x1 = X1[k2], x2 = X2[k2], x3 = X3[k2];
        ulonglong2 wuA = ((const ulonglong2*)(Wu + k2 * 64 + 4 * tx))[0];
        ulonglong2 wuB = ((const ulonglong2*)(Wu + k2 * 64 + 4 * tx))[1];
        fma2(u00, x0, wuA.x); fma2(u01, x0, wuA.y); fma2(u02, x0, wuB.x); fma2(u03, x0, wuB.y);
        fma2(u10, x1, wuA.x); fma2(u11, x1, wuA.y); fma2(u12, x1, wuB.x); fma2(u13, x1, wuB.y);
        fma2(u20, x2, wuA.x); fma2(u21, x2, wuA.y); fma2(u22, x2, wuB.x); fma2(u23, x2, wuB.y);
        fma2(u30, x3, wuA.x); fma2(u31, x3, wuA.y); fma2(u32, x3, wuB.x); fma2(u33, x3, wuB.y);
        ulonglong2 wvA = ((const ulonglong2*)(Wv + k2 * 64 + 4 * tx))[0];
        ulonglong2 wvB = ((const ulonglong2*)(Wv + k2 * 64 + 4 * tx))[1];
        fma2(v00, x0, wvA.x); fma2(v01, x0, wvA.y); fma2(v02, x0, wvB.x); fma2(v03, x0, wvB.y);
        fma2(v10, x1, wvA.x); fma2(v11, x1, wvA.y); fma2(v12, x1, wvB.x); fma2(v13, x1, wvB.y);
        fma2(v20, x2, wvA.x); fma2(v21, x2, wvA.y); fma2(v22, x2, wvB.x); fma2(v23, x2, wvB.y);
        fma2(v30, x3, wvA.x); fma2(v31, x3, wvA.y); fma2(v32, x3, wvB.x); fma2(v33, x3, wvB.y);
    }

    int gr0 = r0g + 4 * ty;
    if (gr0 + 0 < NN) {
        ((float4*)(g_u + (size_t)(gr0+0) * HH))[tx] = make_float4(hsum2(u00), hsum2(u01), hsum2(u02), hsum2(u03));
        ((float4*)(g_v + (size_t)(gr0+0) * HH))[tx] = make_float4(hsum2(v00), hsum2(v01), hsum2(v02), hsum2(v03));
    }
    if (gr0 + 1 < NN) {
        ((float4*)(g_u + (size_t)(gr0+1) * HH))[tx] = make_float4(hsum2(u10), hsum2(u11), hsum2(u12), hsum2(u13));
        ((float4*)(g_v + (size_t)(gr0+1) * HH))[tx] = make_float4(hsum2(v10), hsum2(v11), hsum2(v12), hsum2(v13));
    }
    if (gr0 + 2 < NN) {
        ((float4*)(g_u + (size_t)(gr0+2) * HH))[tx] = make_float4(hsum2(u20), hsum2(u21), hsum2(u22), hsum2(u23));
        ((float4*)(g_v + (size_t)(gr0+2) * HH))[tx] = make_float4(hsum2(v20), hsum2(v21), hsum2(v22), hsum2(v23));
    }
    if (gr0 + 3 < NN) {
        ((float4*)(g_u + (size_t)(gr0+3) * HH))[tx] = make_float4(hsum2(u30), hsum2(u31), hsum2(u32), hsum2(u33));
        ((float4*)(g_v + (size_t)(gr0+3) * HH))[tx] = make_float4(hsum2(v30), hsum2(v31), hsum2(v32), hsum2(v33));
    }
}

// persistent warp-per-2-edges classifier, f32x2, pipelined gathers (R5-proven loop)
__global__ void __launch_bounds__(256) k_classify(const int* __restrict__ src,
                                                  const int* __restrict__ dst,
                                                  const float* __restrict__ ea,
                                                  const float* __restrict__ Wc1,
                                                  const float* __restrict__ bc1,
                                                  const float* __restrict__ Wc2,
                                                  const float* __restrict__ bc2,
                                                  float* __restrict__ out) {
    __shared__ float eas[16][DE];
    int tid = threadIdx.x, lane = tid & 31, w = tid >> 5;

    ull wcol2[DE];
    #pragma unroll
    for (int k = 0; k < DE; k++)
        wcol2[k] = ((const ull*)(Wc1 + 2 * HH * HH + k * HH))[lane];
    ull  b1v  = ((const ull*)bc1)[lane];
    float2 wc2v = ((const float2*)Wc2)[lane];
    float b2 = bc2[0];

    const ull* u2p = (const ull*)g_u;
    const ull* v2p = (const ull*)g_v;

    for (int eb = blockIdx.x * 16; eb < EE; eb += gridDim.x * 16) {  // EE % 16 == 0
        int e0 = eb + 2 * w, e1 = e0 + 1;
        eas[2*w  ][lane] = ea[(size_t)e0 * DE + lane];
        eas[2*w+1][lane] = ea[(size_t)e1 * DE + lane];
        int s0 = src[e0], d0 = dst[e0], s1 = src[e1], d1 = dst[e1];
        ull Ua = u2p[(size_t)s0 * 32 + lane];
        ull Va = v2p[(size_t)d0 * 32 + lane];
        ull Ub = u2p[(size_t)s1 * 32 + lane];
        ull Vb = v2p[(size_t)d1 * 32 + lane];
        __syncwarp();
        ull acc0 = add2(add2(Ua, Va), b1v);
        ull acc1 = add2(add2(Ub, Vb), b1v);
        #pragma unroll
        for (int k = 0; k < DE; k += 2) {
            float2 ex = *(const float2*)&eas[2*w][k];
            float2 ey = *(const float2*)&eas[2*w+1][k];
            fma2(acc0, pk2(ex.x, ex.x), wcol2[k]);
            fma2(acc0, pk2(ex.y, ex.y), wcol2[k + 1]);
            fma2(acc1, pk2(ey.x, ey.x), wcol2[k]);
            fma2(acc1, pk2(ey.y, ey.y), wcol2[k + 1]);
        }
        float2 a0 = upk2(acc0), a1 = upk2(acc1);
        float r0 = fmaxf(a0.x, 0.f) * wc2v.x + fmaxf(a0.y, 0.f) * wc2v.y;
        float r1 = fmaxf(a1.x, 0.f) * wc2v.x + fmaxf(a1.y, 0.f) * wc2v.y;
        #pragma unroll
        for (int o = 16; o > 0; o >>= 1) {
            r0 += __shfl_xor_sync(0xffffffffu, r0, o);
            r1 += __shfl_xor_sync(0xffffffffu, r1, o);
        }
        if (lane == 0) { out[e0] = r0 + b2; out[e1] = r1 + b2; }
        __syncwarp();
    }
}

// ---------------- host launcher ----------------
extern "C" void kernel_launch(void* const* d_in, const int* in_sizes, int n_in,
                              void* d_out, int out_size) {
    const float* x    = (const float*)d_in[0];
    const int*   ei   = (const int*)  d_in[1];
    const float* ea   = (const float*)d_in[2];
    const float* W1   = (const float*)d_in[3];
    const float* We1  = (const float*)d_in[4];
    const float* as1  = (const float*)d_in[5];
    const float* ad1  = (const float*)d_in[6];
    const float* ae1  = (const float*)d_in[7];
    const float* b1   = (const float*)d_in[8];
    const float* W2   = (const float*)d_in[9];
    const float* We2  = (const float*)d_in[10];
    const float* as2  = (const float*)d_in[11];
    const float* ad2  = (const float*)d_in[12];
    const float* ae2  = (const float*)d_in[13];
    const float* b2   = (const float*)d_in[14];
    const float* Wc1  = (const float*)d_in[15];
    const float* bc1  = (const float*)d_in[16];
    const float* Wc2  = (const float*)d_in[17];
    const float* bc2  = (const float*)d_in[18];
    float*       out  = (float*)d_out;

    const int* src = ei;        // edge_index[0]
    const int* dst = ei + EE;   // edge_index[1]

    const int NB_N = (NN + 255) / 256;
    const int NB_E = EE / 256;               // exact
    const int NT64 = (NN + 63) / 64;         // 782
    const int CLS_GRID = 444;                // persistent grid-stride; extra blocks = tail slack

    // smem: DIN=128 -> 32KB W + 32KB X = 64KB (needs opt-in); DIN=64 -> 32KB
    const int SMEM_G1 = (D0 / 2) * 64 * 8 + 64 * D0 * 4;   // 65536
    const int SMEM_G2 = (HH / 2) * 64 * 8 + 64 * HH * 4;   // 32768
    cudaFuncSetAttribute(k_gemm<D0, 0>, cudaFuncAttributeMaxDynamicSharedMemorySize, SMEM_G1);

    k_zero_prep<<<NB_N, 256>>>(We1, ae1, We2, ae2);
    k_hist<<<NB_E, 256>>>(dst);
    k_scanA<<<SCAN_G, SCAN_B>>>();
    k_gemm<D0, 0><<<NT64, 256, SMEM_G1>>>(x, W1, as1, ad1);   // independent of CSR build
    k_scanC<<<SCAN_G, SCAN_B>>>();
    k_scatter_t<<<NB_E, 256>>>(ea, src, dst);

    // ---- GAT layer 1 aggregation ----
    k_attn<0><<<NN / 8, 256>>>(b1);

    // ---- GAT layer 2 ----
    k_gemm<HH, 1><<<NT64, 256, SMEM_G2>>>(nullptr, W2, as2, ad2);
    k_attn<1><<<NN / 8, 256>>>(b2);

    // ---- edge classifier ----
    k_gemm_uv<<<NT64, 256>>>(Wc1);
    k_classify<<<CLS_GRID, 256>>>(src, dst, ea, Wc1, bc1, Wc2, bc2, out);
}

// round 11
// speedup vs baseline: 1.1316x; 1.1316x over previous
#include <cuda_runtime.h>

#define NN 50000
#define EE 800000
#define HH 64
#define D0 128
#define DE 32
#define NEG 0.2f

typedef unsigned long long ull;

// ---------------- scratch (static device globals; no allocation) ----------------
__device__ __align__(16) float g_h  [NN * HH];
__device__ __align__(16) float g_x1 [NN * HH];
__device__ __align__(16) float g_x2 [NN * HH];
__device__ __align__(16) float g_u  [NN * HH];
__device__ __align__(16) float g_v  [NN * HH];
__device__ float g_ssrc[NN], g_sdst[NN];
__device__ int   g_degi[NN];
__device__ int   g_rowptr[NN + 1];
__device__ int   g_rank[EE];               // rank of edge within its dst segment
__device__ int   g_bsum[128];
__device__ __align__(16) float4 g_csr[EE]; // {src_bits, t1, t2, pad} per edge, CSR by dst
__device__ float g_wv1[DE], g_wv2[DE];

__device__ __forceinline__ float lrelu(float z) { return z >= 0.f ? z : NEG * z; }

// ---- packed f32x2 helpers ----
__device__ __forceinline__ ull pk2(float x, float y) {
    ull r; asm("mov.b64 %0, {%1,%2};" : "=l"(r) : "f"(x), "f"(y)); return r;
}
__device__ __forceinline__ void fma2(ull& d, ull a, ull b) {
    asm("fma.rn.f32x2 %0, %1, %2, %0;" : "+l"(d) : "l"(a), "l"(b));
}
__device__ __forceinline__ ull add2(ull a, ull b) {
    ull r; asm("add.rn.f32x2 %0, %1, %2;" : "=l"(r) : "l"(a), "l"(b)); return r;
}
__device__ __forceinline__ float2 upk2(ull v) {
    float2 f; asm("mov.b64 {%0,%1}, %2;" : "=f"(f.x), "=f"(f.y) : "l"(v)); return f;
}
__device__ __forceinline__ float hsum2(ull v) {
    float2 f = upk2(v); return f.x + f.y;
}

// ---------------- zero counters + prep wv = We @ a_edge ----------------
__global__ void k_zero_prep(const float* __restrict__ We1, const float* __restrict__ ae1,
                            const float* __restrict__ We2, const float* __restrict__ ae2) {
    int i = blockIdx.x * blockDim.x + threadIdx.x;
    if (i < NN) g_degi[i] = 0;
    if (i == 0) g_rowptr[NN] = EE;
    if (blockIdx.x == 0 && threadIdx.x >= 32 && threadIdx.x < 64) {
        int k = threadIdx.x - 32;
        float s1 = 0.f, s2 = 0.f;
        #pragma unroll 8
        for (int j = 0; j < HH; j++) {
            s1 = fmaf(We1[k * HH + j], ae1[j], s1);
            s2 = fmaf(We2[k * HH + j], ae2[j], s2);
        }
        g_wv1[k] = s1;
        g_wv2[k] = s2;
    }
}

// degree histogram (dst only) + per-edge rank within dst segment
__global__ void __launch_bounds__(256) k_hist(const int* __restrict__ dst) {
    int e = blockIdx.x * 256 + threadIdx.x;   // grid exactly EE/256
    g_rank[e] = atomicAdd(&g_degi[dst[e]], 1);
}

// ---------------- parallel scan: degi -> rowptr ----------------
#define SCAN_B 512
#define SCAN_G 98          // 98*512 = 50176 >= NN

__global__ void __launch_bounds__(SCAN_B) k_scanA() {
    __shared__ int ws[SCAN_B / 32];
    int idx = blockIdx.x * SCAN_B + threadIdx.x;
    int v = (idx < NN) ? g_degi[idx] : 0;
    int s = v;
    #pragma unroll
    for (int o = 16; o > 0; o >>= 1) s += __shfl_xor_sync(0xffffffffu, s, o);
    if ((threadIdx.x & 31) == 0) ws[threadIdx.x >> 5] = s;
    __syncthreads();
    if (threadIdx.x < SCAN_B / 32) {
        int t = ws[threadIdx.x];
        #pragma unroll
        for (int o = 8; o > 0; o >>= 1) t += __shfl_xor_sync(0xffffu, t, o);
        if (threadIdx.x == 0) g_bsum[blockIdx.x] = t;
    }
}

__global__ void __launch_bounds__(SCAN_B) k_scanC() {
    __shared__ int wsum[4];
    __shared__ int ws[SCAN_B / 32];
    __shared__ int spre;
    int tid = threadIdx.x, lane = tid & 31, w = tid >> 5;
    if (tid < 128) {
        int pv = (tid < blockIdx.x) ? g_bsum[tid] : 0;
        #pragma unroll
        for (int o = 16; o > 0; o >>= 1) pv += __shfl_xor_sync(0xffffffffu, pv, o);
        if (lane == 0) wsum[w] = pv;
    }
    int idx = blockIdx.x * SCAN_B + tid;
    int v = (idx < NN) ? g_degi[idx] : 0;
    int inc = v;
    #pragma unroll
    for (int o = 1; o < 32; o <<= 1) {
        int x = __shfl_up_sync(0xffffffffu, inc, o);
        if (lane >= o) inc += x;
    }
    if (lane == 31) ws[w] = inc;
    __syncthreads();
    if (tid == 0) spre = wsum[0] + wsum[1] + wsum[2] + wsum[3];
    if (w == 0 && lane < SCAN_B / 32) {
        int y = ws[lane];
        #pragma unroll
        for (int o = 1; o < SCAN_B / 32; o <<= 1) {
            int x = __shfl_up_sync(0xffffu, y, o);
            if (lane >= o) y += x;
        }
        ws[lane] = y;
    }
    __syncthreads();
    int off = inc - v + (w > 0 ? ws[w - 1] : 0) + spre;
    if (idx < NN) g_rowptr[idx] = off;
}

// fused: compute t1/t2 from ea, scatter packed 16B CSR record (atomic-free via g_rank)
__global__ void __launch_bounds__(256) k_scatter_t(const float* __restrict__ ea,
                                                   const int* __restrict__ src,
                                                   const int* __restrict__ dst) {
    __shared__ float wv1s[DE], wv2s[DE];
    int tid = threadIdx.x;
    if (tid < DE) { wv1s[tid] = g_wv1[tid]; wv2s[tid] = g_wv2[tid]; }
    __syncthreads();
    int e = blockIdx.x * 256 + tid;           // grid exactly EE/256
    const float4* p = (const float4*)(ea + (size_t)e * DE);
    float t1 = 0.f, t2 = 0.f;
    #pragma unroll
    for (int q = 0; q < 8; q++) {
        float4 v = p[q];
        t1 = fmaf(v.x, wv1s[4*q+0], t1); t1 = fmaf(v.y, wv1s[4*q+1], t1);
        t1 = fmaf(v.z, wv1s[4*q+2], t1); t1 = fmaf(v.w, wv1s[4*q+3], t1);
        t2 = fmaf(v.x, wv2s[4*q+0], t2); t2 = fmaf(v.y, wv2s[4*q+1], t2);
        t2 = fmaf(v.z, wv2s[4*q+2], t2); t2 = fmaf(v.w, wv2s[4*q+3], t2);
    }
    int d = dst[e];
    int pos = g_rowptr[d] + g_rank[e];
    g_csr[pos] = make_float4(__int_as_float(src[e]), t1, t2, 0.f);
}

// ---------------- GEMM: 64x64 tile, thread = 4 rows x 4 cols, packed-k FFMA2 ----------------
// dynamic smem: Wp[(DIN/2)*64] ull, then Xs[64*DIN] float
template <int DIN, int SRC>
__global__ void __launch_bounds__(256, 2) k_gemm(const float* __restrict__ xin_p,
                                                 const float* __restrict__ W,
                                                 const float* __restrict__ as,
                                                 const float* __restrict__ ad) {
    extern __shared__ char sm[];
    ull*   Wp = (ull*)sm;                              // (DIN/2) * 64
    float* Xs = (float*)(sm + (DIN / 2) * 64 * 8);     // 64 * DIN
    const float* xin = SRC ? g_x1 : xin_p;
    int tid = threadIdx.x;

    for (int i = tid; i < (DIN / 2) * 64; i += 256) {
        int k2 = i >> 6, c = i & 63;
        Wp[i] = pk2(W[(2 * k2) * HH + c], W[(2 * k2 + 1) * HH + c]);
    }
    int r0g = blockIdx.x * 64;                         // grid = ceil(NN/64)
    for (int i = tid; i < 64 * DIN / 4; i += 256) {
        int r = i / (DIN / 4), q = i % (DIN / 4);
        float4 vv = (r0g + r < NN) ? ((const float4*)(xin + (size_t)(r0g + r) * DIN))[q]
                                   : make_float4(0.f, 0.f, 0.f, 0.f);
        ((float4*)Xs)[i] = vv;
    }
    __syncthreads();

    int tx = tid & 15, ty = tid >> 4;                  // cols 4tx..4tx+3, rows 4ty..4ty+3
    const ull* X0 = (const ull*)(Xs + (4 * ty + 0) * DIN);
    const ull* X1 = (const ull*)(Xs + (4 * ty + 1) * DIN);
    const ull* X2 = (const ull*)(Xs + (4 * ty + 2) * DIN);
    const ull* X3 = (const ull*)(Xs + (4 * ty + 3) * DIN);

    ull a00=0,a01=0,a02=0,a03=0, a10=0,a11=0,a12=0,a13=0;
    ull a20=0,a21=0,a22=0,a23=0, a30=0,a31=0,a32=0,a33=0;
    #pragma unroll 8
    for (int k2 = 0; k2 < DIN / 2; k2++) {
        ull x0 = X0[k2], x1 = X1[k2], x2 = X2[k2], x3 = X3[k2];
        ulonglong2 wA = ((const ulonglong2*)(Wp + k2 * 64 + 4 * tx))[0];
        ulonglong2 wB = ((const ulonglong2*)(Wp + k2 * 64 + 4 * tx))[1];
        fma2(a00, x0, wA.x); fma2(a01, x0, wA.y); fma2(a02, x0, wB.x); fma2(a03, x0, wB.y);
        fma2(a10, x1, wA.x); fma2(a11, x1, wA.y); fma2(a12, x1, wB.x); fma2(a13, x1, wB.y);
        fma2(a20, x2, wA.x); fma2(a21, x2, wA.y); fma2(a22, x2, wB.x); fma2(a23, x2, wB.y);
        fma2(a30, x3, wA.x); fma2(a31, x3, wA.y); fma2(a32, x3, wB.x); fma2(a33, x3, wB.y);
    }

    float4 res[4];
    res[0] = make_float4(hsum2(a00), hsum2(a01), hsum2(a02), hsum2(a03));
    res[1] = make_float4(hsum2(a10), hsum2(a11), hsum2(a12), hsum2(a13));
    res[2] = make_float4(hsum2(a20), hsum2(a21), hsum2(a22), hsum2(a23));
    res[3] = make_float4(hsum2(a30), hsum2(a31), hsum2(a32), hsum2(a33));

    float4 as4 = ((const float4*)as)[tx];
    float4 ad4 = ((const float4*)ad)[tx];
    float ps[4], pd[4];
    #pragma unroll
    for (int i = 0; i < 4; i++) {
        int gr = r0g + 4 * ty + i;
        if (gr < NN) ((float4*)(g_h + (size_t)gr * HH))[tx] = res[i];
        ps[i] = res[i].x*as4.x + res[i].y*as4.y + res[i].z*as4.z + res[i].w*as4.w;
        pd[i] = res[i].x*ad4.x + res[i].y*ad4.y + res[i].z*ad4.z + res[i].w*ad4.w;
    }
    #pragma unroll
    for (int o = 8; o > 0; o >>= 1) {
        #pragma unroll
        for (int i = 0; i < 4; i++) {
            ps[i] += __shfl_xor_sync(0xffffffffu, ps[i], o);
            pd[i] += __shfl_xor_sync(0xffffffffu, pd[i], o);
        }
    }
    if (tx == 0) {
        #pragma unroll
        for (int i = 0; i < 4; i++) {
            int gr = r0g + 4 * ty + i;
            if (gr < NN) { g_ssrc[gr] = ps[i]; g_sdst[gr] = pd[i]; }
        }
    }
}

// single-pass per-dst softmax + aggregation, packed CSR records (R5-proven loop)
template <int LAYER>
__global__ void __launch_bounds__(256) k_attn(const float* __restrict__ b) {
    int lane = threadIdx.x & 31;
    int n = blockIdx.x * 8 + (threadIdx.x >> 5);   // grid exactly NN/8
    float* xout = LAYER ? g_x2 : g_x1;
    int beg = g_rowptr[n], end = g_rowptr[n + 1];
    float sd = g_sdst[n], ss = g_ssrc[n];

    const ull* h2 = (const ull*)g_h;
    ull acc2 = 0;
    float ssum = 0.f, tsum = 0.f;
    for (int base = beg; base < end; base += 32) {
        int j = base + lane;
        float ev = 0.f; int si = 0;
        if (j < end) {
            float4 rec = g_csr[j];
            si = __float_as_int(rec.x);
            float t = LAYER ? rec.z : rec.y;
            ev = __expf(lrelu(g_ssrc[si] + sd + t));
            tsum += t;
        }
        ssum += ev;
        int cnt = min(32, end - base);
        #pragma unroll 4
        for (int k = 0; k < cnt; k++) {
            int   s = __shfl_sync(0xffffffffu, si, k);
            float w = __shfl_sync(0xffffffffu, ev, k);
            fma2(acc2, pk2(w, w), h2[(size_t)s * 32 + lane]);
        }
    }
    #pragma unroll
    for (int o = 16; o > 0; o >>= 1) {
        ssum += __shfl_xor_sync(0xffffffffu, ssum, o);
        tsum += __shfl_xor_sync(0xffffffffu, tsum, o);
    }

    float deg = (float)(end - beg);
    float tl = tsum / fmaxf(deg, 1.0f);
    float eself = __expf(lrelu(ss + sd + tl));
    float inv = 1.f / (ssum + eself);
    float aself = eself * inv;

    float2 a = upk2(acc2);
    float2 hn = upk2(h2[(size_t)n * 32 + lane]);
    float2 bv = ((const float2*)b)[lane];
    float2 o2;
    o2.x = fmaxf(fmaf(a.x, inv, fmaf(aself, hn.x, bv.x)), 0.f);
    o2.y = fmaxf(fmaf(a.y, inv, fmaf(aself, hn.y, bv.y)), 0.f);
    ((float2*)xout)[(size_t)n * 32 + lane] = o2;
}

// ---------------- classifier ----------------
// u = x2 @ Wc1[0:64], v = x2 @ Wc1[64:128]  — 64x64 tile, 4 rows x 4 cols per thread
__global__ void __launch_bounds__(256, 2) k_gemm_uv(const float* __restrict__ Wc1) {
    __shared__ ull Wu[(HH / 2) * HH];     // 16 KB
    __shared__ ull Wv[(HH / 2) * HH];     // 16 KB
    __shared__ float Xs[64 * HH];         // 16 KB
    int tid = threadIdx.x;
    for (int i = tid; i < (HH / 2) * HH; i += 256) {
        int k2 = i >> 6, c = i & 63;
        Wu[i] = pk2(Wc1[(2 * k2) * HH + c], Wc1[(2 * k2 + 1) * HH + c]);
        Wv[i] = pk2(Wc1[(HH + 2 * k2) * HH + c], Wc1[(HH + 2 * k2 + 1) * HH + c]);
    }
    int r0g = blockIdx.x * 64;                        // grid = ceil(NN/64)
    for (int i = tid; i < 64 * HH / 4; i += 256) {
        int r = i / (HH / 4), q = i % (HH / 4);
        float4 vv = (r0g + r < NN) ? ((const float4*)(g_x2 + (size_t)(r0g + r) * HH))[q]
                                   : make_float4(0.f, 0.f, 0.f, 0.f);
        ((float4*)Xs)[i] = vv;
    }
    __syncthreads();

    int tx = tid & 15, ty = tid >> 4;
    const ull* X0 = (const ull*)(Xs + (4 * ty + 0) * HH);
    const ull* X1 = (const ull*)(Xs + (4 * ty + 1) * HH);
    const ull* X2 = (const ull*)(Xs + (4 * ty + 2) * HH);
    const ull* X3 = (const ull*)(Xs + (4 * ty + 3) * HH);

    ull u00=0,u01=0,u02=0,u03=0, u10=0,u11=0,u12=0,u13=0;
    ull u20=0,u21=0,u22=0,u23=0, u30=0,u31=0,u32=0,u33=0;
    ull v00=0,v01=0,v02=0,v03=0, v10=0,v11=0,v12=0,v13=0;
    ull v20=0,v21=0,v22=0,v23=0, v30=0,v31=0,v32=0,v33=0;
    #pragma unroll 4
    for (int k2 = 0; k2 < HH / 2; k2++) {
        ull x0 = X0[k2], x1 = X1[k2], x2 = X2[k2], x3 = X3[k2];
        ulonglong2 wuA = ((const ulonglong2*)(Wu + k2 * 64 + 4 * tx))[0];
        ulonglong2 wuB = ((const ulonglong2*)(Wu + k2 * 64 + 4 * tx))[1];
        fma2(u00, x0, wuA.x); fma2(u01, x0, wuA.y); fma2(u02, x0, wuB.x); fma2(u03, x0, wuB.y);
        fma2(u10, x1, wuA.x); fma2(u11, x1, wuA.y); fma2(u12, x1, wuB.x); fma2(u13, x1, wuB.y);
        fma2(u20, x2, wuA.x); fma2(u21, x2, wuA.y); fma2(u22, x2, wuB.x); fma2(u23, x2, wuB.y);
        fma2(u30, x3, wuA.x); fma2(u31, x3, wuA.y); fma2(u32, x3, wuB.x); fma2(u33, x3, wuB.y);
        ulonglong2 wvA = ((const ulonglong2*)(Wv + k2 * 64 + 4 * tx))[0];
        ulonglong2 wvB = ((const ulonglong2*)(Wv + k2 * 64 + 4 * tx))[1];
        fma2(v00, x0, wvA.x); fma2(v01, x0, wvA.y); fma2(v02, x0, wvB.x); fma2(v03, x0, wvB.y);
        fma2(v10, x1, wvA.x); fma2(v11, x1, wvA.y); fma2(v12, x1, wvB.x); fma2(v13, x1, wvB.y);
        fma2(v20, x2, wvA.x); fma2(v21, x2, wvA.y); fma2(v22, x2, wvB.x); fma2(v23, x2, wvB.y);
        fma2(v30, x3, wvA.x); fma2(v31, x3, wvA.y); fma2(v32, x3, wvB.x); fma2(v33, x3, wvB.y);
    }

    int gr0 = r0g + 4 * ty;
    if (gr0 + 0 < NN) {
        ((float4*)(g_u + (size_t)(gr0+0) * HH))[tx] = make_float4(hsum2(u00), hsum2(u01), hsum2(u02), hsum2(u03));
        ((float4*)(g_v + (size_t)(gr0+0) * HH))[tx] = make_float4(hsum2(v00), hsum2(v01), hsum2(v02), hsum2(v03));
    }
    if (gr0 + 1 < NN) {
        ((float4*)(g_u + (size_t)(gr0+1) * HH))[tx] = make_float4(hsum2(u10), hsum2(u11), hsum2(u12), hsum2(u13));
        ((float4*)(g_v + (size_t)(gr0+1) * HH))[tx] = make_float4(hsum2(v10), hsum2(v11), hsum2(v12), hsum2(v13));
    }
    if (gr0 + 2 < NN) {
        ((float4*)(g_u + (size_t)(gr0+2) * HH))[tx] = make_float4(hsum2(u20), hsum2(u21), hsum2(u22), hsum2(u23));
        ((float4*)(g_v + (size_t)(gr0+2) * HH))[tx] = make_float4(hsum2(v20), hsum2(v21), hsum2(v22), hsum2(v23));
    }
    if (gr0 + 3 < NN) {
        ((float4*)(g_u + (size_t)(gr0+3) * HH))[tx] = make_float4(hsum2(u30), hsum2(u31), hsum2(u32), hsum2(u33));
        ((float4*)(g_v + (size_t)(gr0+3) * HH))[tx] = make_float4(hsum2(v30), hsum2(v31), hsum2(v32), hsum2(v33));
    }
}

// persistent warp-per-2-edges classifier, f32x2, pipelined gathers (R5-proven loop)
__global__ void __launch_bounds__(256) k_classify(const int* __restrict__ src,
                                                  const int* __restrict__ dst,
                                                  const float* __restrict__ ea,
                                                  const float* __restrict__ Wc1,
                                                  const float* __restrict__ bc1,
                                                  const float* __restrict__ Wc2,
                                                  const float* __restrict__ bc2,
                                                  float* __restrict__ out) {
    __shared__ float eas[16][DE];
    int tid = threadIdx.x, lane = tid & 31, w = tid >> 5;

    ull wcol2[DE];
    #pragma unroll
    for (int k = 0; k < DE; k++)
        wcol2[k] = ((const ull*)(Wc1 + 2 * HH * HH + k * HH))[lane];
    ull  b1v  = ((const ull*)bc1)[lane];
    float2 wc2v = ((const float2*)Wc2)[lane];
    float b2 = bc2[0];

    const ull* u2p = (const ull*)g_u;
    const ull* v2p = (const ull*)g_v;

    for (int eb = blockIdx.x * 16; eb < EE; eb += gridDim.x * 16) {  // EE % 16 == 0
        int e0 = eb + 2 * w, e1 = e0 + 1;
        eas[2*w  ][lane] = ea[(size_t)e0 * DE + lane];
        eas[2*w+1][lane] = ea[(size_t)e1 * DE + lane];
        int s0 = src[e0], d0 = dst[e0], s1 = src[e1], d1 = dst[e1];
        ull Ua = u2p[(size_t)s0 * 32 + lane];
        ull Va = v2p[(size_t)d0 * 32 + lane];
        ull Ub = u2p[(size_t)s1 * 32 + lane];
        ull Vb = v2p[(size_t)d1 * 32 + lane];
        __syncwarp();
        ull acc0 = add2(add2(Ua, Va), b1v);
        ull acc1 = add2(add2(Ub, Vb), b1v);
        #pragma unroll
        for (int k = 0; k < DE; k += 2) {
            float2 ex = *(const float2*)&eas[2*w][k];
            float2 ey = *(const float2*)&eas[2*w+1][k];
            fma2(acc0, pk2(ex.x, ex.x), wcol2[k]);
            fma2(acc0, pk2(ex.y, ex.y), wcol2[k + 1]);
            fma2(acc1, pk2(ey.x, ey.x), wcol2[k]);
            fma2(acc1, pk2(ey.y, ey.y), wcol2[k + 1]);
        }
        float2 a0 = upk2(acc0), a1 = upk2(acc1);
        float r0 = fmaxf(a0.x, 0.f) * wc2v.x + fmaxf(a0.y, 0.f) * wc2v.y;
        float r1 = fmaxf(a1.x, 0.f) * wc2v.x + fmaxf(a1.y, 0.f) * wc2v.y;
        #pragma unroll
        for (int o = 16; o > 0; o >>= 1) {
            r0 += __shfl_xor_sync(0xffffffffu, r0, o);
            r1 += __shfl_xor_sync(0xffffffffu, r1, o);
        }
        if (lane == 0) { out[e0] = r0 + b2; out[e1] = r1 + b2; }
        __syncwarp();
    }
}

// ---------------- host launcher ----------------
extern "C" void kernel_launch(void* const* d_in, const int* in_sizes, int n_in,
                              void* d_out, int out_size) {
    const float* x    = (const float*)d_in[0];
    const int*   ei   = (const int*)  d_in[1];
    const float* ea   = (const float*)d_in[2];
    const float* W1   = (const float*)d_in[3];
    const float* We1  = (const float*)d_in[4];
    const float* as1  = (const float*)d_in[5];
    const float* ad1  = (const float*)d_in[6];
    const float* ae1  = (const float*)d_in[7];
    const float* b1   = (const float*)d_in[8];
    const float* W2   = (const float*)d_in[9];
    const float* We2  = (const float*)d_in[10];
    const float* as2  = (const float*)d_in[11];
    const float* ad2  = (const float*)d_in[12];
    const float* ae2  = (const float*)d_in[13];
    const float* b2   = (const float*)d_in[14];
    const float* Wc1  = (const float*)d_in[15];
    const float* bc1  = (const float*)d_in[16];
    const float* Wc2  = (const float*)d_in[17];
    const float* bc2  = (const float*)d_in[18];
    float*       out  = (float*)d_out;

    const int* src = ei;        // edge_index[0]
    const int* dst = ei + EE;   // edge_index[1]

    const int NB_N = (NN + 255) / 256;
    const int NB_E = EE / 256;               // exact
    const int NT64 = (NN + 63) / 64;         // 782
    const int CLS_GRID = 296;                // == resident blocks (2/SM x 148): single wave

    // smem: DIN=128 -> 32KB W + 32KB X = 64KB (needs opt-in); DIN=64 -> 32KB
    const int SMEM_G1 = (D0 / 2) * 64 * 8 + 64 * D0 * 4;   // 65536
    const int SMEM_G2 = (HH / 2) * 64 * 8 + 64 * HH * 4;   // 32768
    cudaFuncSetAttribute(k_gemm<D0, 0>, cudaFuncAttributeMaxDynamicSharedMemorySize, SMEM_G1);

    k_zero_prep<<<NB_N, 256>>>(We1, ae1, We2, ae2);
    k_hist<<<NB_E, 256>>>(dst);
    k_scanA<<<SCAN_G, SCAN_B>>>();
    k_gemm<D0, 0><<<NT64, 256, SMEM_G1>>>(x, W1, as1, ad1);   // independent of CSR build
    k_scanC<<<SCAN_G, SCAN_B>>>();
    k_scatter_t<<<NB_E, 256>>>(ea, src, dst);

    // ---- GAT layer 1 aggregation ----
    k_attn<0><<<NN / 8, 256>>>(b1);

    // ---- GAT layer 2 ----
    k_gemm<HH, 1><<<NT64, 256, SMEM_G2>>>(nullptr, W2, as2, ad2);
    k_attn<1><<<NN / 8, 256>>>(b2);

    // ---- edge classifier ----
    k_gemm_uv<<<NT64, 256>>>(Wc1);
    k_classify<<<CLS_GRID, 256>>>(src, dst, ea, Wc1, bc1, Wc2, bc2, out);
}

// round 12
// speedup vs baseline: 1.1557x; 1.0214x over previous
#include <cuda_runtime.h>

#define NN 50000
#define EE 800000
#define HH 64
#define D0 128
#define DE 32
#define NEG 0.2f

typedef unsigned long long ull;

// ---------------- scratch (static device globals; no allocation) ----------------
__device__ __align__(16) float g_h  [NN * HH];
__device__ __align__(16) float g_x1 [NN * HH];
__device__ __align__(16) float g_x2 [NN * HH];
__device__ __align__(16) float g_u  [NN * HH];
__device__ __align__(16) float g_v  [NN * HH];
__device__ float g_ssrc[NN], g_sdst[NN];
__device__ int   g_degi[NN];
__device__ int   g_rowptr[NN + 1];
__device__ int   g_rank[EE];               // rank of edge within its dst segment
__device__ int   g_bsum[128];
__device__ __align__(16) float4 g_csr[EE]; // {src_bits, t1, t2, pad} per edge, CSR by dst
__device__ float g_wv1[DE], g_wv2[DE];
// pre-packed f32x2 weights (filled once by k_pack)
__device__ __align__(16) ull g_Wp1[(D0 / 2) * HH];   // W1 packed (k-pair, col)
__device__ __align__(16) ull g_Wp2[(HH / 2) * HH];   // W2 packed
__device__ __align__(16) ull g_Wpu[(HH / 2) * HH];   // Wc1[0:64]
__device__ __align__(16) ull g_Wpv[(HH / 2) * HH];   // Wc1[64:128]
__device__ __align__(16) ull g_Wpb[DE * 32];         // Wc1[128:160]: [k][lane] col pair

__device__ __forceinline__ float lrelu(float z) { return z >= 0.f ? z : NEG * z; }

// ---- packed f32x2 helpers ----
__device__ __forceinline__ ull pk2(float x, float y) {
    ull r; asm("mov.b64 %0, {%1,%2};" : "=l"(r) : "f"(x), "f"(y)); return r;
}
__device__ __forceinline__ void fma2(ull& d, ull a, ull b) {
    asm("fma.rn.f32x2 %0, %1, %2, %0;" : "+l"(d) : "l"(a), "l"(b));
}
__device__ __forceinline__ ull add2(ull a, ull b) {
    ull r; asm("add.rn.f32x2 %0, %1, %2;" : "=l"(r) : "l"(a), "l"(b)); return r;
}
__device__ __forceinline__ float2 upk2(ull v) {
    float2 f; asm("mov.b64 {%0,%1}, %2;" : "=f"(f.x), "=f"(f.y) : "l"(v)); return f;
}
__device__ __forceinline__ float hsum2(ull v) {
    float2 f = upk2(v); return f.x + f.y;
}

// ---------------- one-shot weight packing ----------------
__global__ void __launch_bounds__(256) k_pack(const float* __restrict__ W1,
                                              const float* __restrict__ W2,
                                              const float* __restrict__ Wc1) {
    int i = blockIdx.x * 256 + threadIdx.x;          // grid covers 11264
    if (i < 4096) {                                   // Wp1: (D0/2)*64
        int k2 = i >> 6, c = i & 63;
        g_Wp1[i] = pk2(W1[(2 * k2) * HH + c], W1[(2 * k2 + 1) * HH + c]);
    } else if (i < 6144) {
        int j = i - 4096, k2 = j >> 6, c = j & 63;
        g_Wp2[j] = pk2(W2[(2 * k2) * HH + c], W2[(2 * k2 + 1) * HH + c]);
    } else if (i < 8192) {
        int j = i - 6144, k2 = j >> 6, c = j & 63;
        g_Wpu[j] = pk2(Wc1[(2 * k2) * HH + c], Wc1[(2 * k2 + 1) * HH + c]);
    } else if (i < 10240) {
        int j = i - 8192, k2 = j >> 6, c = j & 63;
        g_Wpv[j] = pk2(Wc1[(HH + 2 * k2) * HH + c], Wc1[(HH + 2 * k2 + 1) * HH + c]);
    } else if (i < 10240 + DE * 32) {
        int j = i - 10240, k = j >> 5, lane = j & 31;
        const float* p = Wc1 + 2 * HH * HH + k * HH + 2 * lane;
        g_Wpb[j] = pk2(p[0], p[1]);
    }
}

// ---------------- zero counters + prep wv = We @ a_edge ----------------
__global__ void k_zero_prep(const float* __restrict__ We1, const float* __restrict__ ae1,
                            const float* __restrict__ We2, const float* __restrict__ ae2) {
    int i = blockIdx.x * blockDim.x + threadIdx.x;
    if (i < NN) g_degi[i] = 0;
    if (i == 0) g_rowptr[NN] = EE;
    if (blockIdx.x == 0 && threadIdx.x >= 32 && threadIdx.x < 64) {
        int k = threadIdx.x - 32;
        float s1 = 0.f, s2 = 0.f;
        #pragma unroll 8
        for (int j = 0; j < HH; j++) {
            s1 = fmaf(We1[k * HH + j], ae1[j], s1);
            s2 = fmaf(We2[k * HH + j], ae2[j], s2);
        }
        g_wv1[k] = s1;
        g_wv2[k] = s2;
    }
}

// degree histogram (dst only) + per-edge rank within dst segment
__global__ void __launch_bounds__(256) k_hist(const int* __restrict__ dst) {
    int e = blockIdx.x * 256 + threadIdx.x;   // grid exactly EE/256
    g_rank[e] = atomicAdd(&g_degi[dst[e]], 1);
}

// ---------------- parallel scan: degi -> rowptr ----------------
#define SCAN_B 512
#define SCAN_G 98          // 98*512 = 50176 >= NN

__global__ void __launch_bounds__(SCAN_B) k_scanA() {
    __shared__ int ws[SCAN_B / 32];
    int idx = blockIdx.x * SCAN_B + threadIdx.x;
    int v = (idx < NN) ? g_degi[idx] : 0;
    int s = v;
    #pragma unroll
    for (int o = 16; o > 0; o >>= 1) s += __shfl_xor_sync(0xffffffffu, s, o);
    if ((threadIdx.x & 31) == 0) ws[threadIdx.x >> 5] = s;
    __syncthreads();
    if (threadIdx.x < SCAN_B / 32) {
        int t = ws[threadIdx.x];
        #pragma unroll
        for (int o = 8; o > 0; o >>= 1) t += __shfl_xor_sync(0xffffu, t, o);
        if (threadIdx.x == 0) g_bsum[blockIdx.x] = t;
    }
}

__global__ void __launch_bounds__(SCAN_B) k_scanC() {
    __shared__ int wsum[4];
    __shared__ int ws[SCAN_B / 32];
    __shared__ int spre;
    int tid = threadIdx.x, lane = tid & 31, w = tid >> 5;
    if (tid < 128) {
        int pv = (tid < blockIdx.x) ? g_bsum[tid] : 0;
        #pragma unroll
        for (int o = 16; o > 0; o >>= 1) pv += __shfl_xor_sync(0xffffffffu, pv, o);
        if (lane == 0) wsum[w] = pv;
    }
    int idx = blockIdx.x * SCAN_B + tid;
    int v = (idx < NN) ? g_degi[idx] : 0;
    int inc = v;
    #pragma unroll
    for (int o = 1; o < 32; o <<= 1) {
        int x = __shfl_up_sync(0xffffffffu, inc, o);
        if (lane >= o) inc += x;
    }
    if (lane == 31) ws[w] = inc;
    __syncthreads();
    if (tid == 0) spre = wsum[0] + wsum[1] + wsum[2] + wsum[3];
    if (w == 0 && lane < SCAN_B / 32) {
        int y = ws[lane];
        #pragma unroll
        for (int o = 1; o < SCAN_B / 32; o <<= 1) {
            int x = __shfl_up_sync(0xffffu, y, o);
            if (lane >= o) y += x;
        }
        ws[lane] = y;
    }
    __syncthreads();
    int off = inc - v + (w > 0 ? ws[w - 1] : 0) + spre;
    if (idx < NN) g_rowptr[idx] = off;
}

// fused: compute t1/t2 from ea, scatter packed 16B CSR record (atomic-free via g_rank)
__global__ void __launch_bounds__(256) k_scatter_t(const float* __restrict__ ea,
                                                   const int* __restrict__ src,
                                                   const int* __restrict__ dst) {
    __shared__ float wv1s[DE], wv2s[DE];
    int tid = threadIdx.x;
    if (tid < DE) { wv1s[tid] = g_wv1[tid]; wv2s[tid] = g_wv2[tid]; }
    __syncthreads();
    int e = blockIdx.x * 256 + tid;           // grid exactly EE/256
    const float4* p = (const float4*)(ea + (size_t)e * DE);
    float t1 = 0.f, t2 = 0.f;
    #pragma unroll
    for (int q = 0; q < 8; q++) {
        float4 v = p[q];
        t1 = fmaf(v.x, wv1s[4*q+0], t1); t1 = fmaf(v.y, wv1s[4*q+1], t1);
        t1 = fmaf(v.z, wv1s[4*q+2], t1); t1 = fmaf(v.w, wv1s[4*q+3], t1);
        t2 = fmaf(v.x, wv2s[4*q+0], t2); t2 = fmaf(v.y, wv2s[4*q+1], t2);
        t2 = fmaf(v.z, wv2s[4*q+2], t2); t2 = fmaf(v.w, wv2s[4*q+3], t2);
    }
    int d = dst[e];
    int pos = g_rowptr[d] + g_rank[e];
    g_csr[pos] = make_float4(__int_as_float(src[e]), t1, t2, 0.f);
}

// ---------------- GEMM: 64x64 tile, thread = 4 rows x 4 cols, packed-k FFMA2 ----------------
// dynamic smem: Wp[(DIN/2)*64] ull, then Xs[64*DIN] float; W copied pre-packed from global
template <int DIN, int SRC>
__global__ void __launch_bounds__(256, 2) k_gemm(const float* __restrict__ xin_p,
                                                 const ull* __restrict__ Wp_g,
                                                 const float* __restrict__ as,
                                                 const float* __restrict__ ad) {
    extern __shared__ char sm[];
    ull*   Wp = (ull*)sm;                              // (DIN/2) * 64
    float* Xs = (float*)(sm + (DIN / 2) * 64 * 8);     // 64 * DIN
    const float* xin = SRC ? g_x1 : xin_p;
    int tid = threadIdx.x;

    for (int i = tid; i < (DIN / 2) * 64 / 2; i += 256)
        ((ulonglong2*)Wp)[i] = ((const ulonglong2*)Wp_g)[i];
    int r0g = blockIdx.x * 64;                         // grid = ceil(NN/64)
    for (int i = tid; i < 64 * DIN / 4; i += 256) {
        int r = i / (DIN / 4), q = i % (DIN / 4);
        float4 vv = (r0g + r < NN) ? ((const float4*)(xin + (size_t)(r0g + r) * DIN))[q]
                                   : make_float4(0.f, 0.f, 0.f, 0.f);
        ((float4*)Xs)[i] = vv;
    }
    __syncthreads();

    int tx = tid & 15, ty = tid >> 4;                  // cols 4tx..4tx+3, rows 4ty..4ty+3
    const ull* X0 = (const ull*)(Xs + (4 * ty + 0) * DIN);
    const ull* X1 = (const ull*)(Xs + (4 * ty + 1) * DIN);
    const ull* X2 = (const ull*)(Xs + (4 * ty + 2) * DIN);
    const ull* X3 = (const ull*)(Xs + (4 * ty + 3) * DIN);

    ull a00=0,a01=0,a02=0,a03=0, a10=0,a11=0,a12=0,a13=0;
    ull a20=0,a21=0,a22=0,a23=0, a30=0,a31=0,a32=0,a33=0;
    #pragma unroll 8
    for (int k2 = 0; k2 < DIN / 2; k2++) {
        ull x0 = X0[k2], x1 = X1[k2], x2 = X2[k2], x3 = X3[k2];
        ulonglong2 wA = ((const ulonglong2*)(Wp + k2 * 64 + 4 * tx))[0];
        ulonglong2 wB = ((const ulonglong2*)(Wp + k2 * 64 + 4 * tx))[1];
        fma2(a00, x0, wA.x); fma2(a01, x0, wA.y); fma2(a02, x0, wB.x); fma2(a03, x0, wB.y);
        fma2(a10, x1, wA.x); fma2(a11, x1, wA.y); fma2(a12, x1, wB.x); fma2(a13, x1, wB.y);
        fma2(a20, x2, wA.x); fma2(a21, x2, wA.y); fma2(a22, x2, wB.x); fma2(a23, x2, wB.y);
        fma2(a30, x3, wA.x); fma2(a31, x3, wA.y); fma2(a32, x3, wB.x); fma2(a33, x3, wB.y);
    }

    float4 res[4];
    res[0] = make_float4(hsum2(a00), hsum2(a01), hsum2(a02), hsum2(a03));
    res[1] = make_float4(hsum2(a10), hsum2(a11), hsum2(a12), hsum2(a13));
    res[2] = make_float4(hsum2(a20), hsum2(a21), hsum2(a22), hsum2(a23));
    res[3] = make_float4(hsum2(a30), hsum2(a31), hsum2(a32), hsum2(a33));

    float4 as4 = ((const float4*)as)[tx];
    float4 ad4 = ((const float4*)ad)[tx];
    float ps[4], pd[4];
    #pragma unroll
    for (int i = 0; i < 4; i++) {
        int gr = r0g + 4 * ty + i;
        if (gr < NN) ((float4*)(g_h + (size_t)gr * HH))[tx] = res[i];
        ps[i] = res[i].x*as4.x + res[i].y*as4.y + res[i].z*as4.z + res[i].w*as4.w;
        pd[i] = res[i].x*ad4.x + res[i].y*ad4.y + res[i].z*ad4.z + res[i].w*ad4.w;
    }
    #pragma unroll
    for (int o = 8; o > 0; o >>= 1) {
        #pragma unroll
        for (int i = 0; i < 4; i++) {
            ps[i] += __shfl_xor_sync(0xffffffffu, ps[i], o);
            pd[i] += __shfl_xor_sync(0xffffffffu, pd[i], o);
        }
    }
    if (tx == 0) {
        #pragma unroll
        for (int i = 0; i < 4; i++) {
            int gr = r0g + 4 * ty + i;
            if (gr < NN) { g_ssrc[gr] = ps[i]; g_sdst[gr] = pd[i]; }
        }
    }
}

// single-pass per-dst softmax + aggregation, packed CSR records (R5-proven loop)
template <int LAYER>
__global__ void __launch_bounds__(256) k_attn(const float* __restrict__ b) {
    int lane = threadIdx.x & 31;
    int n = blockIdx.x * 8 + (threadIdx.x >> 5);   // grid exactly NN/8
    float* xout = LAYER ? g_x2 : g_x1;
    int beg = g_rowptr[n], end = g_rowptr[n + 1];
    float sd = g_sdst[n], ss = g_ssrc[n];

    const ull* h2 = (const ull*)g_h;
    ull acc2 = 0;
    float ssum = 0.f, tsum = 0.f;
    for (int base = beg; base < end; base += 32) {
        int j = base + lane;
        float ev = 0.f; int si = 0;
        if (j < end) {
            float4 rec = g_csr[j];
            si = __float_as_int(rec.x);
            float t = LAYER ? rec.z : rec.y;
            ev = __expf(lrelu(g_ssrc[si] + sd + t));
            tsum += t;
        }
        ssum += ev;
        int cnt = min(32, end - base);
        #pragma unroll 4
        for (int k = 0; k < cnt; k++) {
            int   s = __shfl_sync(0xffffffffu, si, k);
            float w = __shfl_sync(0xffffffffu, ev, k);
            fma2(acc2, pk2(w, w), h2[(size_t)s * 32 + lane]);
        }
    }
    #pragma unroll
    for (int o = 16; o > 0; o >>= 1) {
        ssum += __shfl_xor_sync(0xffffffffu, ssum, o);
        tsum += __shfl_xor_sync(0xffffffffu, tsum, o);
    }

    float deg = (float)(end - beg);
    float tl = tsum / fmaxf(deg, 1.0f);
    float eself = __expf(lrelu(ss + sd + tl));
    float inv = 1.f / (ssum + eself);
    float aself = eself * inv;

    float2 a = upk2(acc2);
    float2 hn = upk2(h2[(size_t)n * 32 + lane]);
    float2 bv = ((const float2*)b)[lane];
    float2 o2;
    o2.x = fmaxf(fmaf(a.x, inv, fmaf(aself, hn.x, bv.x)), 0.f);
    o2.y = fmaxf(fmaf(a.y, inv, fmaf(aself, hn.y, bv.y)), 0.f);
    ((float2*)xout)[(size_t)n * 32 + lane] = o2;
}

// ---------------- classifier ----------------
// u = x2 @ Wc1[0:64], v = x2 @ Wc1[64:128]  — 64x64 tile, weights copied pre-packed
__global__ void __launch_bounds__(256, 2) k_gemm_uv() {
    __shared__ ull Wu[(HH / 2) * HH];     // 16 KB
    __shared__ ull Wv[(HH / 2) * HH];     // 16 KB
    __shared__ float Xs[64 * HH];         // 16 KB
    int tid = threadIdx.x;
    for (int i = tid; i < (HH / 2) * HH / 2; i += 256) {
        ((ulonglong2*)Wu)[i] = ((const ulonglong2*)g_Wpu)[i];
        ((ulonglong2*)Wv)[i] = ((const ulonglong2*)g_Wpv)[i];
    }
    int r0g = blockIdx.x * 64;                        // grid = ceil(NN/64)
    for (int i = tid; i < 64 * HH / 4; i += 256) {
        int r = i / (HH / 4), q = i % (HH / 4);
        float4 vv = (r0g + r < NN) ? ((const float4*)(g_x2 + (size_t)(r0g + r) * HH))[q]
                                   : make_float4(0.f, 0.f, 0.f, 0.f);
        ((float4*)Xs)[i] = vv;
    }
    __syncthreads();

    int tx = tid & 15, ty = tid >> 4;
    const ull* X0 = (const ull*)(Xs + (4 * ty + 0) * HH);
    const ull* X1 = (const ull*)(Xs + (4 * ty + 1) * HH);
    const ull* X2 = (const ull*)(Xs + (4 * ty + 2) * HH);
    const ull* X3 = (const ull*)(Xs + (4 * ty + 3) * HH);

    ull u00=0,u01=0,u02=0,u03=0, u10=0,u11=0,u12=0,u13=0;
    ull u20=0,u21=0,u22=0,u23=0, u30=0,u31=0,u32=0,u33=0;
    ull v00=0,v01=0,v02=0,v03=0, v10=0,v11=0,v12=0,v13=0;
    ull v20=0,v21=0,v22=0,v23=0, v30=0,v31=0,v32=0,v33=0;
    #pragma unroll 4
    for (int k2 = 0; k2 < HH / 2; k2++) {
        ull x0 = X0[k2], x1 = X1[k2], x2 = X2[k2], x3 = X3[k2];
        ulonglong2 wuA = ((const ulonglong2*)(Wu + k2 * 64 + 4 * tx))[0];
        ulonglong2 wuB = ((const ulonglong2*)(Wu + k2 * 64 + 4 * tx))[1];
        fma2(u00, x0, wuA.x); fma2(u01, x0, wuA.y); fma2(u02, x0, wuB.x); fma2(u03, x0, wuB.y);
        fma2(u10, x1, wuA.x); fma2(u11, x1, wuA.y); fma2(u12, x1, wuB.x); fma2(u13, x1, wuB.y);
        fma2(u20, x2, wuA.x); fma2(u21, x2, wuA.y); fma2(u22, x2, wuB.x); fma2(u23, x2, wuB.y);
        fma2(u30, x3, wuA.x); fma2(u31, x3, wuA.y); fma2(u32, x3, wuB.x); fma2(u33, x3, wuB.y);
        ulonglong2 wvA = ((const ulonglong2*)(Wv + k2 * 64 + 4 * tx))[0];
        ulonglong2 wvB = ((const ulonglong2*)(Wv + k2 * 64 + 4 * tx))[1];
        fma2(v00, x0, wvA.x); fma2(v01, x0, wvA.y); fma2(v02, x0, wvB.x); fma2(v03, x0, wvB.y);
        fma2(v10, x1, wvA.x); fma2(v11, x1, wvA.y); fma2(v12, x1, wvB.x); fma2(v13, x1, wvB.y);
        fma2(v20, x2, wvA.x); fma2(v21, x2, wvA.y); fma2(v22, x2, wvB.x); fma2(v23, x2, wvB.y);
        fma2(v30, x3, wvA.x); fma2(v31, x3, wvA.y); fma2(v32, x3, wvB.x); fma2(v33, x3, wvB.y);
    }

    int gr0 = r0g + 4 * ty;
    if (gr0 + 0 < NN) {
        ((float4*)(g_u + (size_t)(gr0+0) * HH))[tx] = make_float4(hsum2(u00), hsum2(u01), hsum2(u02), hsum2(u03));
        ((float4*)(g_v + (size_t)(gr0+0) * HH))[tx] = make_float4(hsum2(v00), hsum2(v01), hsum2(v02), hsum2(v03));
    }
    if (gr0 + 1 < NN) {
        ((float4*)(g_u + (size_t)(gr0+1) * HH))[tx] = make_float4(hsum2(u10), hsum2(u11), hsum2(u12), hsum2(u13));
        ((float4*)(g_v + (size_t)(gr0+1) * HH))[tx] = make_float4(hsum2(v10), hsum2(v11), hsum2(v12), hsum2(v13));
    }
    if (gr0 + 2 < NN) {
        ((float4*)(g_u + (size_t)(gr0+2) * HH))[tx] = make_float4(hsum2(u20), hsum2(u21), hsum2(u22), hsum2(u23));
        ((float4*)(g_v + (size_t)(gr0+2) * HH))[tx] = make_float4(hsum2(v20), hsum2(v21), hsum2(v22), hsum2(v23));
    }
    if (gr0 + 3 < NN) {
        ((float4*)(g_u + (size_t)(gr0+3) * HH))[tx] = make_float4(hsum2(u30), hsum2(u31), hsum2(u32), hsum2(u33));
        ((float4*)(g_v + (size_t)(gr0+3) * HH))[tx] = make_float4(hsum2(v30), hsum2(v31), hsum2(v32), hsum2(v33));
    }
}

// persistent warp-per-2-edges classifier, f32x2, pipelined gathers (R5-proven loop;
// weight cache loaded coalesced from pre-packed global)
__global__ void __launch_bounds__(256) k_classify(const int* __restrict__ src,
                                                  const int* __restrict__ dst,
                                                  const float* __restrict__ ea,
                                                  const float* __restrict__ bc1,
                                                  const float* __restrict__ Wc2,
                                                  const float* __restrict__ bc2,
                                                  float* __restrict__ out) {
    __shared__ float eas[16][DE];
    int tid = threadIdx.x, lane = tid & 31, w = tid >> 5;

    ull wcol2[DE];
    #pragma unroll
    for (int k = 0; k < DE; k++)
        wcol2[k] = g_Wpb[k * 32 + lane];
    ull  b1v  = ((const ull*)bc1)[lane];
    float2 wc2v = ((const float2*)Wc2)[lane];
    float b2 = bc2[0];

    const ull* u2p = (const ull*)g_u;
    const ull* v2p = (const ull*)g_v;

    for (int eb = blockIdx.x * 16; eb < EE; eb += gridDim.x * 16) {  // EE % 16 == 0
        int e0 = eb + 2 * w, e1 = e0 + 1;
        eas[2*w  ][lane] = ea[(size_t)e0 * DE + lane];
        eas[2*w+1][lane] = ea[(size_t)e1 * DE + lane];
        int s0 = src[e0], d0 = dst[e0], s1 = src[e1], d1 = dst[e1];
        ull Ua = u2p[(size_t)s0 * 32 + lane];
        ull Va = v2p[(size_t)d0 * 32 + lane];
        ull Ub = u2p[(size_t)s1 * 32 + lane];
        ull Vb = v2p[(size_t)d1 * 32 + lane];
        __syncwarp();
        ull acc0 = add2(add2(Ua, Va), b1v);
        ull acc1 = add2(add2(Ub, Vb), b1v);
        #pragma unroll
        for (int k = 0; k < DE; k += 2) {
            float2 ex = *(const float2*)&eas[2*w][k];
            float2 ey = *(const float2*)&eas[2*w+1][k];
            fma2(acc0, pk2(ex.x, ex.x), wcol2[k]);
            fma2(acc0, pk2(ex.y, ex.y), wcol2[k + 1]);
            fma2(acc1, pk2(ey.x, ey.x), wcol2[k]);
            fma2(acc1, pk2(ey.y, ey.y), wcol2[k + 1]);
        }
        float2 a0 = upk2(acc0), a1 = upk2(acc1);
        float r0 = fmaxf(a0.x, 0.f) * wc2v.x + fmaxf(a0.y, 0.f) * wc2v.y;
        float r1 = fmaxf(a1.x, 0.f) * wc2v.x + fmaxf(a1.y, 0.f) * wc2v.y;
        #pragma unroll
        for (int o = 16; o > 0; o >>= 1) {
            r0 += __shfl_xor_sync(0xffffffffu, r0, o);
            r1 += __shfl_xor_sync(0xffffffffu, r1, o);
        }
        if (lane == 0) { out[e0] = r0 + b2; out[e1] = r1 + b2; }
        __syncwarp();
    }
}

// ---------------- host launcher ----------------
extern "C" void kernel_launch(void* const* d_in, const int* in_sizes, int n_in,
                              void* d_out, int out_size) {
    const float* x    = (const float*)d_in[0];
    const int*   ei   = (const int*)  d_in[1];
    const float* ea   = (const float*)d_in[2];
    const float* W1   = (const float*)d_in[3];
    const float* We1  = (const float*)d_in[4];
    const float* as1  = (const float*)d_in[5];
    const float* ad1  = (const float*)d_in[6];
    const float* ae1  = (const float*)d_in[7];
    const float* b1   = (const float*)d_in[8];
    const float* W2   = (const float*)d_in[9];
    const float* We2  = (const float*)d_in[10];
    const float* as2  = (const float*)d_in[11];
    const float* ad2  = (const float*)d_in[12];
    const float* ae2  = (const float*)d_in[13];
    const float* b2   = (const float*)d_in[14];
    const float* Wc1  = (const float*)d_in[15];
    const float* bc1  = (const float*)d_in[16];
    const float* Wc2  = (const float*)d_in[17];
    const float* bc2  = (const float*)d_in[18];
    float*       out  = (float*)d_out;

    const int* src = ei;        // edge_index[0]
    const int* dst = ei + EE;   // edge_index[1]

    const int NB_N = (NN + 255) / 256;
    const int NB_E = EE / 256;               // exact
    const int NT64 = (NN + 63) / 64;         // 782
    const int CLS_GRID = 296;                // == resident blocks (2/SM x 148): single wave

    // smem: DIN=128 -> 32KB W + 32KB X = 64KB (needs opt-in); DIN=64 -> 32KB
    const int SMEM_G1 = (D0 / 2) * 64 * 8 + 64 * D0 * 4;   // 65536
    const int SMEM_G2 = (HH / 2) * 64 * 8 + 64 * HH * 4;   // 32768
    cudaFuncSetAttribute(k_gemm<D0, 0>, cudaFuncAttributeMaxDynamicSharedMemorySize, SMEM_G1);

    // weight pre-pack (44*256 = 11264 >= 10240 + DE*32)
    k_pack<<<44, 256>>>(W1, W2, Wc1);
    // device-side pointers to packed W for k_gemm args
    ull* wp1; cudaGetSymbolAddress((void**)&wp1, g_Wp1);
    ull* wp2; cudaGetSymbolAddress((void**)&wp2, g_Wp2);

    k_zero_prep<<<NB_N, 256>>>(We1, ae1, We2, ae2);
    k_hist<<<NB_E, 256>>>(dst);
    k_scanA<<<SCAN_G, SCAN_B>>>();
    k_gemm<D0, 0><<<NT64, 256, SMEM_G1>>>(x, wp1, as1, ad1);   // independent of CSR build
    k_scanC<<<SCAN_G, SCAN_B>>>();
    k_scatter_t<<<NB_E, 256>>>(ea, src, dst);

    // ---- GAT layer 1 aggregation ----
    k_attn<0><<<NN / 8, 256>>>(b1);

    // ---- GAT layer 2 ----
    k_gemm<HH, 1><<<NT64, 256, SMEM_G2>>>(nullptr, wp2, as2, ad2);
    k_attn<1><<<NN / 8, 256>>>(b2);

    // ---- edge classifier ----
    k_gemm_uv<<<NT64, 256>>>();
    k_classify<<<CLS_GRID, 256>>>(src, dst, ea, bc1, Wc2, bc2, out);
}

// round 13
// speedup vs baseline: 1.1727x; 1.0147x over previous
#include <cuda_runtime.h>

#define NN 50000
#define EE 800000
#define HH 64
#define D0 128
#define DE 32
#define NEG 0.2f

typedef unsigned long long ull;

// ---------------- scratch (static device globals; no allocation) ----------------
__device__ __align__(16) float g_h  [NN * HH];
__device__ __align__(16) float g_x1 [NN * HH];
__device__ __align__(16) float g_x2 [NN * HH];
__device__ __align__(16) float g_u  [NN * HH];
__device__ __align__(16) float g_v  [NN * HH];
__device__ float g_ssrc[NN], g_sdst[NN];
__device__ int   g_degi[NN];
__device__ int   g_rowptr[NN + 1];
__device__ int   g_rank[EE];               // rank of edge within its dst segment
__device__ int   g_bsum[128];
__device__ __align__(16) float4 g_csr[EE]; // {src_bits, t1, t2, pad} per edge, CSR by dst
__device__ float g_wv1[DE], g_wv2[DE];
// pre-packed f32x2 weights (filled once in k_zero_prep)
__device__ __align__(16) ull g_Wp1[(D0 / 2) * HH];   // W1 packed (k-pair, col)
__device__ __align__(16) ull g_Wp2[(HH / 2) * HH];   // W2 packed
__device__ __align__(16) ull g_Wpu[(HH / 2) * HH];   // Wc1[0:64]
__device__ __align__(16) ull g_Wpv[(HH / 2) * HH];   // Wc1[64:128]
__device__ __align__(16) ull g_Wpb[DE * 32];         // Wc1[128:160]: [k][lane] col pair

__device__ __forceinline__ float lrelu(float z) { return z >= 0.f ? z : NEG * z; }

// ---- packed f32x2 helpers ----
__device__ __forceinline__ ull pk2(float x, float y) {
    ull r; asm("mov.b64 %0, {%1,%2};" : "=l"(r) : "f"(x), "f"(y)); return r;
}
__device__ __forceinline__ void fma2(ull& d, ull a, ull b) {
    asm("fma.rn.f32x2 %0, %1, %2, %0;" : "+l"(d) : "l"(a), "l"(b));
}
__device__ __forceinline__ ull add2(ull a, ull b) {
    ull r; asm("add.rn.f32x2 %0, %1, %2;" : "=l"(r) : "l"(a), "l"(b)); return r;
}
__device__ __forceinline__ float2 upk2(ull v) {
    float2 f; asm("mov.b64 {%0,%1}, %2;" : "=f"(f.x), "=f"(f.y) : "l"(v)); return f;
}
__device__ __forceinline__ float hsum2(ull v) {
    float2 f = upk2(v); return f.x + f.y;
}

// ---------------- zero counters + wv = We @ a_edge + weight pre-pack ----------------
// grid = max(NB_N, 44) blocks x 256
__global__ void k_zero_prep(const float* __restrict__ We1, const float* __restrict__ ae1,
                            const float* __restrict__ We2, const float* __restrict__ ae2,
                            const float* __restrict__ W1, const float* __restrict__ W2,
                            const float* __restrict__ Wc1) {
    int i = blockIdx.x * blockDim.x + threadIdx.x;
    if (i < NN) g_degi[i] = 0;
    if (i == 0) g_rowptr[NN] = EE;
    if (blockIdx.x == 0 && threadIdx.x >= 32 && threadIdx.x < 64) {
        int k = threadIdx.x - 32;
        float s1 = 0.f, s2 = 0.f;
        #pragma unroll 8
        for (int j = 0; j < HH; j++) {
            s1 = fmaf(We1[k * HH + j], ae1[j], s1);
            s2 = fmaf(We2[k * HH + j], ae2[j], s2);
        }
        g_wv1[k] = s1;
        g_wv2[k] = s2;
    }
    // weight pre-pack (first 11264 threads)
    if (i < 4096) {                                   // Wp1: (D0/2)*64
        int k2 = i >> 6, c = i & 63;
        g_Wp1[i] = pk2(W1[(2 * k2) * HH + c], W1[(2 * k2 + 1) * HH + c]);
    } else if (i < 6144) {
        int j = i - 4096, k2 = j >> 6, c = j & 63;
        g_Wp2[j] = pk2(W2[(2 * k2) * HH + c], W2[(2 * k2 + 1) * HH + c]);
    } else if (i < 8192) {
        int j = i - 6144, k2 = j >> 6, c = j & 63;
        g_Wpu[j] = pk2(Wc1[(2 * k2) * HH + c], Wc1[(2 * k2 + 1) * HH + c]);
    } else if (i < 10240) {
        int j = i - 8192, k2 = j >> 6, c = j & 63;
        g_Wpv[j] = pk2(Wc1[(HH + 2 * k2) * HH + c], Wc1[(HH + 2 * k2 + 1) * HH + c]);
    } else if (i < 10240 + DE * 32) {
        int j = i - 10240, k = j >> 5, lane = j & 31;
        const float* p = Wc1 + 2 * HH * HH + k * HH + 2 * lane;
        g_Wpb[j] = pk2(p[0], p[1]);
    }
}

// degree histogram (dst only) + per-edge rank within dst segment
__global__ void __launch_bounds__(256) k_hist(const int* __restrict__ dst) {
    int e = blockIdx.x * 256 + threadIdx.x;   // grid exactly EE/256
    g_rank[e] = atomicAdd(&g_degi[dst[e]], 1);
}

// ---------------- parallel scan: degi -> rowptr ----------------
#define SCAN_B 512
#define SCAN_G 98          // 98*512 = 50176 >= NN

__global__ void __launch_bounds__(SCAN_B) k_scanA() {
    __shared__ int ws[SCAN_B / 32];
    int idx = blockIdx.x * SCAN_B + threadIdx.x;
    int v = (idx < NN) ? g_degi[idx] : 0;
    int s = v;
    #pragma unroll
    for (int o = 16; o > 0; o >>= 1) s += __shfl_xor_sync(0xffffffffu, s, o);
    if ((threadIdx.x & 31) == 0) ws[threadIdx.x >> 5] = s;
    __syncthreads();
    if (threadIdx.x < SCAN_B / 32) {
        int t = ws[threadIdx.x];
        #pragma unroll
        for (int o = 8; o > 0; o >>= 1) t += __shfl_xor_sync(0xffffu, t, o);
        if (threadIdx.x == 0) g_bsum[blockIdx.x] = t;
    }
}

__global__ void __launch_bounds__(SCAN_B) k_scanC() {
    __shared__ int wsum[4];
    __shared__ int ws[SCAN_B / 32];
    __shared__ int spre;
    int tid = threadIdx.x, lane = tid & 31, w = tid >> 5;
    if (tid < 128) {
        int pv = (tid < blockIdx.x) ? g_bsum[tid] : 0;
        #pragma unroll
        for (int o = 16; o > 0; o >>= 1) pv += __shfl_xor_sync(0xffffffffu, pv, o);
        if (lane == 0) wsum[w] = pv;
    }
    int idx = blockIdx.x * SCAN_B + tid;
    int v = (idx < NN) ? g_degi[idx] : 0;
    int inc = v;
    #pragma unroll
    for (int o = 1; o < 32; o <<= 1) {
        int x = __shfl_up_sync(0xffffffffu, inc, o);
        if (lane >= o) inc += x;
    }
    if (lane == 31) ws[w] = inc;
    __syncthreads();
    if (tid == 0) spre = wsum[0] + wsum[1] + wsum[2] + wsum[3];
    if (w == 0 && lane < SCAN_B / 32) {
        int y = ws[lane];
        #pragma unroll
        for (int o = 1; o < SCAN_B / 32; o <<= 1) {
            int x = __shfl_up_sync(0xffffu, y, o);
            if (lane >= o) y += x;
        }
        ws[lane] = y;
    }
    __syncthreads();
    int off = inc - v + (w > 0 ? ws[w - 1] : 0) + spre;
    if (idx < NN) g_rowptr[idx] = off;
}

// fused: compute t1/t2 from ea, scatter packed 16B CSR record (atomic-free via g_rank)
__global__ void __launch_bounds__(256) k_scatter_t(const float* __restrict__ ea,
                                                   const int* __restrict__ src,
                                                   const int* __restrict__ dst) {
    __shared__ float wv1s[DE], wv2s[DE];
    int tid = threadIdx.x;
    if (tid < DE) { wv1s[tid] = g_wv1[tid]; wv2s[tid] = g_wv2[tid]; }
    __syncthreads();
    int e = blockIdx.x * 256 + tid;           // grid exactly EE/256
    const float4* p = (const float4*)(ea + (size_t)e * DE);
    float t1 = 0.f, t2 = 0.f;
    #pragma unroll
    for (int q = 0; q < 8; q++) {
        float4 v = p[q];
        t1 = fmaf(v.x, wv1s[4*q+0], t1); t1 = fmaf(v.y, wv1s[4*q+1], t1);
        t1 = fmaf(v.z, wv1s[4*q+2], t1); t1 = fmaf(v.w, wv1s[4*q+3], t1);
        t2 = fmaf(v.x, wv2s[4*q+0], t2); t2 = fmaf(v.y, wv2s[4*q+1], t2);
        t2 = fmaf(v.z, wv2s[4*q+2], t2); t2 = fmaf(v.w, wv2s[4*q+3], t2);
    }
    int d = dst[e];
    int pos = g_rowptr[d] + g_rank[e];
    g_csr[pos] = make_float4(__int_as_float(src[e]), t1, t2, 0.f);
}

// ---------------- GEMM: 64x64 tile, thread = 4 rows x 4 cols, packed-k FFMA2 ----------------
// dynamic smem: Wp[(DIN/2)*64] ull, then Xs[64*DIN] float; W copied pre-packed from global.
// 3 blocks/SM (regs capped ~85) — kernel is latency-bound at 2 blocks.
template <int DIN, int SRC>
__global__ void __launch_bounds__(256, 3) k_gemm(const float* __restrict__ xin_p,
                                                 const ull* __restrict__ Wp_g,
                                                 const float* __restrict__ as,
                                                 const float* __restrict__ ad) {
    extern __shared__ char sm[];
    ull*   Wp = (ull*)sm;                              // (DIN/2) * 64
    float* Xs = (float*)(sm + (DIN / 2) * 64 * 8);     // 64 * DIN
    const float* xin = SRC ? g_x1 : xin_p;
    int tid = threadIdx.x;

    for (int i = tid; i < (DIN / 2) * 64 / 2; i += 256)
        ((ulonglong2*)Wp)[i] = ((const ulonglong2*)Wp_g)[i];
    int r0g = blockIdx.x * 64;                         // grid = ceil(NN/64)
    for (int i = tid; i < 64 * DIN / 4; i += 256) {
        int r = i / (DIN / 4), q = i % (DIN / 4);
        float4 vv = (r0g + r < NN) ? ((const float4*)(xin + (size_t)(r0g + r) * DIN))[q]
                                   : make_float4(0.f, 0.f, 0.f, 0.f);
        ((float4*)Xs)[i] = vv;
    }
    __syncthreads();

    int tx = tid & 15, ty = tid >> 4;                  // cols 4tx..4tx+3, rows 4ty..4ty+3
    const ull* X0 = (const ull*)(Xs + (4 * ty + 0) * DIN);
    const ull* X1 = (const ull*)(Xs + (4 * ty + 1) * DIN);
    const ull* X2 = (const ull*)(Xs + (4 * ty + 2) * DIN);
    const ull* X3 = (const ull*)(Xs + (4 * ty + 3) * DIN);

    ull a00=0,a01=0,a02=0,a03=0, a10=0,a11=0,a12=0,a13=0;
    ull a20=0,a21=0,a22=0,a23=0, a30=0,a31=0,a32=0,a33=0;
    #pragma unroll 8
    for (int k2 = 0; k2 < DIN / 2; k2++) {
        ull x0 = X0[k2], x1 = X1[k2], x2 = X2[k2], x3 = X3[k2];
        ulonglong2 wA = ((const ulonglong2*)(Wp + k2 * 64 + 4 * tx))[0];
        ulonglong2 wB = ((const ulonglong2*)(Wp + k2 * 64 + 4 * tx))[1];
        fma2(a00, x0, wA.x); fma2(a01, x0, wA.y); fma2(a02, x0, wB.x); fma2(a03, x0, wB.y);
        fma2(a10, x1, wA.x); fma2(a11, x1, wA.y); fma2(a12, x1, wB.x); fma2(a13, x1, wB.y);
        fma2(a20, x2, wA.x); fma2(a21, x2, wA.y); fma2(a22, x2, wB.x); fma2(a23, x2, wB.y);
        fma2(a30, x3, wA.x); fma2(a31, x3, wA.y); fma2(a32, x3, wB.x); fma2(a33, x3, wB.y);
    }

    float4 res[4];
    res[0] = make_float4(hsum2(a00), hsum2(a01), hsum2(a02), hsum2(a03));
    res[1] = make_float4(hsum2(a10), hsum2(a11), hsum2(a12), hsum2(a13));
    res[2] = make_float4(hsum2(a20), hsum2(a21), hsum2(a22), hsum2(a23));
    res[3] = make_float4(hsum2(a30), hsum2(a31), hsum2(a32), hsum2(a33));

    float4 as4 = ((const float4*)as)[tx];
    float4 ad4 = ((const float4*)ad)[tx];
    float ps[4], pd[4];
    #pragma unroll
    for (int i = 0; i < 4; i++) {
        int gr = r0g + 4 * ty + i;
        if (gr < NN) ((float4*)(g_h + (size_t)gr * HH))[tx] = res[i];
        ps[i] = res[i].x*as4.x + res[i].y*as4.y + res[i].z*as4.z + res[i].w*as4.w;
        pd[i] = res[i].x*ad4.x + res[i].y*ad4.y + res[i].z*ad4.z + res[i].w*ad4.w;
    }
    #pragma unroll
    for (int o = 8; o > 0; o >>= 1) {
        #pragma unroll
        for (int i = 0; i < 4; i++) {
            ps[i] += __shfl_xor_sync(0xffffffffu, ps[i], o);
            pd[i] += __shfl_xor_sync(0xffffffffu, pd[i], o);
        }
    }
    if (tx == 0) {
        #pragma unroll
        for (int i = 0; i < 4; i++) {
            int gr = r0g + 4 * ty + i;
            if (gr < NN) { g_ssrc[gr] = ps[i]; g_sdst[gr] = pd[i]; }
        }
    }
}

// single-pass per-dst softmax + aggregation, packed CSR records (R5-proven loop)
template <int LAYER>
__global__ void __launch_bounds__(256) k_attn(const float* __restrict__ b) {
    int lane = threadIdx.x & 31;
    int n = blockIdx.x * 8 + (threadIdx.x >> 5);   // grid exactly NN/8
    float* xout = LAYER ? g_x2 : g_x1;
    int beg = g_rowptr[n], end = g_rowptr[n + 1];
    float sd = g_sdst[n], ss = g_ssrc[n];

    const ull* h2 = (const ull*)g_h;
    ull acc2 = 0;
    float ssum = 0.f, tsum = 0.f;
    for (int base = beg; base < end; base += 32) {
        int j = base + lane;
        float ev = 0.f; int si = 0;
        if (j < end) {
            float4 rec = g_csr[j];
            si = __float_as_int(rec.x);
            float t = LAYER ? rec.z : rec.y;
            ev = __expf(lrelu(g_ssrc[si] + sd + t));
            tsum += t;
        }
        ssum += ev;
        int cnt = min(32, end - base);
        #pragma unroll 4
        for (int k = 0; k < cnt; k++) {
            int   s = __shfl_sync(0xffffffffu, si, k);
            float w = __shfl_sync(0xffffffffu, ev, k);
            fma2(acc2, pk2(w, w), h2[(size_t)s * 32 + lane]);
        }
    }
    #pragma unroll
    for (int o = 16; o > 0; o >>= 1) {
        ssum += __shfl_xor_sync(0xffffffffu, ssum, o);
        tsum += __shfl_xor_sync(0xffffffffu, tsum, o);
    }

    float deg = (float)(end - beg);
    float tl = tsum / fmaxf(deg, 1.0f);
    float eself = __expf(lrelu(ss + sd + tl));
    float inv = 1.f / (ssum + eself);
    float aself = eself * inv;

    float2 a = upk2(acc2);
    float2 hn = upk2(h2[(size_t)n * 32 + lane]);
    float2 bv = ((const float2*)b)[lane];
    float2 o2;
    o2.x = fmaxf(fmaf(a.x, inv, fmaf(aself, hn.x, bv.x)), 0.f);
    o2.y = fmaxf(fmaf(a.y, inv, fmaf(aself, hn.y, bv.y)), 0.f);
    ((float2*)xout)[(size_t)n * 32 + lane] = o2;
}

// ---------------- classifier ----------------
// u = x2 @ Wc1[0:64], v = x2 @ Wc1[64:128]  — 64x64 tile, weights copied pre-packed
__global__ void __launch_bounds__(256, 2) k_gemm_uv() {
    __shared__ ull Wu[(HH / 2) * HH];     // 16 KB
    __shared__ ull Wv[(HH / 2) * HH];     // 16 KB
    __shared__ float Xs[64 * HH];         // 16 KB
    int tid = threadIdx.x;
    for (int i = tid; i < (HH / 2) * HH / 2; i += 256) {
        ((ulonglong2*)Wu)[i] = ((const ulonglong2*)g_Wpu)[i];
        ((ulonglong2*)Wv)[i] = ((const ulonglong2*)g_Wpv)[i];
    }
    int r0g = blockIdx.x * 64;                        // grid = ceil(NN/64)
    for (int i = tid; i < 64 * HH / 4; i += 256) {
        int r = i / (HH / 4), q = i % (HH / 4);
        float4 vv = (r0g + r < NN) ? ((const float4*)(g_x2 + (size_t)(r0g + r) * HH))[q]
                                   : make_float4(0.f, 0.f, 0.f, 0.f);
        ((float4*)Xs)[i] = vv;
    }
    __syncthreads();

    int tx = tid & 15, ty = tid >> 4;
    const ull* X0 = (const ull*)(Xs + (4 * ty + 0) * HH);
    const ull* X1 = (const ull*)(Xs + (4 * ty + 1) * HH);
    const ull* X2 = (const ull*)(Xs + (4 * ty + 2) * HH);
    const ull* X3 = (const ull*)(Xs + (4 * ty + 3) * HH);

    ull u00=0,u01=0,u02=0,u03=0, u10=0,u11=0,u12=0,u13=0;
    ull u20=0,u21=0,u22=0,u23=0, u30=0,u31=0,u32=0,u33=0;
    ull v00=0,v01=0,v02=0,v03=0, v10=0,v11=0,v12=0,v13=0;
    ull v20=0,v21=0,v22=0,v23=0, v30=0,v31=0,v32=0,v33=0;
    #pragma unroll 4
    for (int k2 = 0; k2 < HH / 2; k2++) {
        ull x0 = X0[k2], x1 = X1[k2], x2 = X2[k2], x3 = X3[k2];
        ulonglong2 wuA = ((const ulonglong2*)(Wu + k2 * 64 + 4 * tx))[0];
        ulonglong2 wuB = ((const ulonglong2*)(Wu + k2 * 64 + 4 * tx))[1];
        fma2(u00, x0, wuA.x); fma2(u01, x0, wuA.y); fma2(u02, x0, wuB.x); fma2(u03, x0, wuB.y);
        fma2(u10, x1, wuA.x); fma2(u11, x1, wuA.y); fma2(u12, x1, wuB.x); fma2(u13, x1, wuB.y);
        fma2(u20, x2, wuA.x); fma2(u21, x2, wuA.y); fma2(u22, x2, wuB.x); fma2(u23, x2, wuB.y);
        fma2(u30, x3, wuA.x); fma2(u31, x3, wuA.y); fma2(u32, x3, wuB.x); fma2(u33, x3, wuB.y);
        ulonglong2 wvA = ((const ulonglong2*)(Wv + k2 * 64 + 4 * tx))[0];
        ulonglong2 wvB = ((const ulonglong2*)(Wv + k2 * 64 + 4 * tx))[1];
        fma2(v00, x0, wvA.x); fma2(v01, x0, wvA.y); fma2(v02, x0, wvB.x); fma2(v03, x0, wvB.y);
        fma2(v10, x1, wvA.x); fma2(v11, x1, wvA.y); fma2(v12, x1, wvB.x); fma2(v13, x1, wvB.y);
        fma2(v20, x2, wvA.x); fma2(v21, x2, wvA.y); fma2(v22, x2, wvB.x); fma2(v23, x2, wvB.y);
        fma2(v30, x3, wvA.x); fma2(v31, x3, wvA.y); fma2(v32, x3, wvB.x); fma2(v33, x3, wvB.y);
    }

    int gr0 = r0g + 4 * ty;
    if (gr0 + 0 < NN) {
        ((float4*)(g_u + (size_t)(gr0+0) * HH))[tx] = make_float4(hsum2(u00), hsum2(u01), hsum2(u02), hsum2(u03));
        ((float4*)(g_v + (size_t)(gr0+0) * HH))[tx] = make_float4(hsum2(v00), hsum2(v01), hsum2(v02), hsum2(v03));
    }
    if (gr0 + 1 < NN) {
        ((float4*)(g_u + (size_t)(gr0+1) * HH))[tx] = make_float4(hsum2(u10), hsum2(u11), hsum2(u12), hsum2(u13));
        ((float4*)(g_v + (size_t)(gr0+1) * HH))[tx] = make_float4(hsum2(v10), hsum2(v11), hsum2(v12), hsum2(v13));
    }
    if (gr0 + 2 < NN) {
        ((float4*)(g_u + (size_t)(gr0+2) * HH))[tx] = make_float4(hsum2(u20), hsum2(u21), hsum2(u22), hsum2(u23));
        ((float4*)(g_v + (size_t)(gr0+2) * HH))[tx] = make_float4(hsum2(v20), hsum2(v21), hsum2(v22), hsum2(v23));
    }
    if (gr0 + 3 < NN) {
        ((float4*)(g_u + (size_t)(gr0+3) * HH))[tx] = make_float4(hsum2(u30), hsum2(u31), hsum2(u32), hsum2(u33));
        ((float4*)(g_v + (size_t)(gr0+3) * HH))[tx] = make_float4(hsum2(v30), hsum2(v31), hsum2(v32), hsum2(v33));
    }
}

// persistent warp-per-2-edges classifier, f32x2, pipelined gathers (R5-proven loop)
__global__ void __launch_bounds__(256) k_classify(const int* __restrict__ src,
                                                  const int* __restrict__ dst,
                                                  const float* __restrict__ ea,
                                                  const float* __restrict__ bc1,
                                                  const float* __restrict__ Wc2,
                                                  const float* __restrict__ bc2,
                                                  float* __restrict__ out) {
    __shared__ float eas[16][DE];
    int tid = threadIdx.x, lane = tid & 31, w = tid >> 5;

    ull wcol2[DE];
    #pragma unroll
    for (int k = 0; k < DE; k++)
        wcol2[k] = g_Wpb[k * 32 + lane];
    ull  b1v  = ((const ull*)bc1)[lane];
    float2 wc2v = ((const float2*)Wc2)[lane];
    float b2 = bc2[0];

    const ull* u2p = (const ull*)g_u;
    const ull* v2p = (const ull*)g_v;

    for (int eb = blockIdx.x * 16; eb < EE; eb += gridDim.x * 16) {  // EE % 16 == 0
        int e0 = eb + 2 * w, e1 = e0 + 1;
        eas[2*w  ][lane] = ea[(size_t)e0 * DE + lane];
        eas[2*w+1][lane] = ea[(size_t)e1 * DE + lane];
        int s0 = src[e0], d0 = dst[e0], s1 = src[e1], d1 = dst[e1];
        ull Ua = u2p[(size_t)s0 * 32 + lane];
        ull Va = v2p[(size_t)d0 * 32 + lane];
        ull Ub = u2p[(size_t)s1 * 32 + lane];
        ull Vb = v2p[(size_t)d1 * 32 + lane];
        __syncwarp();
        ull acc0 = add2(add2(Ua, Va), b1v);
        ull acc1 = add2(add2(Ub, Vb), b1v);
        #pragma unroll
        for (int k = 0; k < DE; k += 2) {
            float2 ex = *(const float2*)&eas[2*w][k];
            float2 ey = *(const float2*)&eas[2*w+1][k];
            fma2(acc0, pk2(ex.x, ex.x), wcol2[k]);
            fma2(acc0, pk2(ex.y, ex.y), wcol2[k + 1]);
            fma2(acc1, pk2(ey.x, ey.x), wcol2[k]);
            fma2(acc1, pk2(ey.y, ey.y), wcol2[k + 1]);
        }
        float2 a0 = upk2(acc0), a1 = upk2(acc1);
        float r0 = fmaxf(a0.x, 0.f) * wc2v.x + fmaxf(a0.y, 0.f) * wc2v.y;
        float r1 = fmaxf(a1.x, 0.f) * wc2v.x + fmaxf(a1.y, 0.f) * wc2v.y;
        #pragma unroll
        for (int o = 16; o > 0; o >>= 1) {
            r0 += __shfl_xor_sync(0xffffffffu, r0, o);
            r1 += __shfl_xor_sync(0xffffffffu, r1, o);
        }
        if (lane == 0) { out[e0] = r0 + b2; out[e1] = r1 + b2; }
        __syncwarp();
    }
}

// ---------------- host launcher ----------------
extern "C" void kernel_launch(void* const* d_in, const int* in_sizes, int n_in,
                              void* d_out, int out_size) {
    const float* x    = (const float*)d_in[0];
    const int*   ei   = (const int*)  d_in[1];
    const float* ea   = (const float*)d_in[2];
    const float* W1   = (const float*)d_in[3];
    const float* We1  = (const float*)d_in[4];
    const float* as1  = (const float*)d_in[5];
    const float* ad1  = (const float*)d_in[6];
    const float* ae1  = (const float*)d_in[7];
    const float* b1   = (const float*)d_in[8];
    const float* W2   = (const float*)d_in[9];
    const float* We2  = (const float*)d_in[10];
    const float* as2  = (const float*)d_in[11];
    const float* ad2  = (const float*)d_in[12];
    const float* ae2  = (const float*)d_in[13];
    const float* b2   = (const float*)d_in[14];
    const float* Wc1  = (const float*)d_in[15];
    const float* bc1  = (const float*)d_in[16];
    const float* Wc2  = (const float*)d_in[17];
    const float* bc2  = (const float*)d_in[18];
    float*       out  = (float*)d_out;

    const int* src = ei;        // edge_index[0]
    const int* dst = ei + EE;   // edge_index[1]

    const int NB_N = (NN + 255) / 256;       // 196 >= 44 (pack coverage)
    const int NB_E = EE / 256;               // exact
    const int NT64 = (NN + 63) / 64;         // 782
    const int CLS_GRID = 296;                // == resident blocks (2/SM x 148): single wave

    // smem: DIN=128 -> 32KB W + 32KB X = 64KB (needs opt-in); DIN=64 -> 32KB
    const int SMEM_G1 = (D0 / 2) * 64 * 8 + 64 * D0 * 4;   // 65536
    const int SMEM_G2 = (HH / 2) * 64 * 8 + 64 * HH * 4;   // 32768
    cudaFuncSetAttribute(k_gemm<D0, 0>, cudaFuncAttributeMaxDynamicSharedMemorySize, SMEM_G1);

    ull* wp1; cudaGetSymbolAddress((void**)&wp1, g_Wp1);
    ull* wp2; cudaGetSymbolAddress((void**)&wp2, g_Wp2);

    k_zero_prep<<<NB_N, 256>>>(We1, ae1, We2, ae2, W1, W2, Wc1);
    k_hist<<<NB_E, 256>>>(dst);
    k_scanA<<<SCAN_G, SCAN_B>>>();
    k_gemm<D0, 0><<<NT64, 256, SMEM_G1>>>(x, wp1, as1, ad1);   // independent of CSR build
    k_scanC<<<SCAN_G, SCAN_B>>>();
    k_scatter_t<<<NB_E, 256>>>(ea, src, dst);

    // ---- GAT layer 1 aggregation ----
    k_attn<0><<<NN / 8, 256>>>(b1);

    // ---- GAT layer 2 ----
    k_gemm<HH, 1><<<NT64, 256, SMEM_G2>>>(nullptr, wp2, as2, ad2);
    k_attn<1><<<NN / 8, 256>>>(b2);

    // ---- edge classifier ----
    k_gemm_uv<<<NT64, 256>>>();
    k_classify<<<CLS_GRID, 256>>>(src, dst, ea, bc1, Wc2, bc2, out);
}

// round 14
// speedup vs baseline: 1.2017x; 1.0247x over previous
#include <cuda_runtime.h>

#define NN 50000
#define EE 800000
#define HH 64
#define D0 128
#define DE 32
#define NEG 0.2f

typedef unsigned long long ull;

// ---------------- scratch (static device globals; no allocation) ----------------
__device__ __align__(16) float g_h  [NN * HH];
__device__ __align__(16) float g_x1 [NN * HH];
__device__ __align__(16) float g_x2 [NN * HH];
__device__ __align__(16) float g_u  [NN * HH];
__device__ __align__(16) float g_v  [NN * HH];
__device__ float g_ssrc[NN], g_sdst[NN];
__device__ int   g_degi[NN];
__device__ int   g_rowptr[NN + 1];
__device__ int   g_rank[EE];               // rank of edge within its dst segment
__device__ int   g_bsum[128];
__device__ __align__(16) float4 g_csr[EE]; // {src_bits, t1, t2, pad} per edge, CSR by dst
__device__ float g_wv1[DE], g_wv2[DE];
// pre-packed f32x2 weights (filled once in k_zero_prep)
__device__ __align__(16) ull g_Wp1[(D0 / 2) * HH];   // W1 packed (k-pair, col)
__device__ __align__(16) ull g_Wp2[(HH / 2) * HH];   // W2 packed
__device__ __align__(16) ull g_Wpu[(HH / 2) * HH];   // Wc1[0:64]
__device__ __align__(16) ull g_Wpv[(HH / 2) * HH];   // Wc1[64:128]
__device__ __align__(16) ull g_Wpb[DE * 32];         // Wc1[128:160]: [k][lane] col pair

__device__ __forceinline__ float lrelu(float z) { return z >= 0.f ? z : NEG * z; }

// ---- packed f32x2 helpers ----
__device__ __forceinline__ ull pk2(float x, float y) {
    ull r; asm("mov.b64 %0, {%1,%2};" : "=l"(r) : "f"(x), "f"(y)); return r;
}
__device__ __forceinline__ void fma2(ull& d, ull a, ull b) {
    asm("fma.rn.f32x2 %0, %1, %2, %0;" : "+l"(d) : "l"(a), "l"(b));
}
__device__ __forceinline__ ull add2(ull a, ull b) {
    ull r; asm("add.rn.f32x2 %0, %1, %2;" : "=l"(r) : "l"(a), "l"(b)); return r;
}
__device__ __forceinline__ float2 upk2(ull v) {
    float2 f; asm("mov.b64 {%0,%1}, %2;" : "=f"(f.x), "=f"(f.y) : "l"(v)); return f;
}
__device__ __forceinline__ float hsum2(ull v) {
    float2 f = upk2(v); return f.x + f.y;
}

// ---------------- zero counters + wv = We @ a_edge + weight pre-pack ----------------
__global__ void k_zero_prep(const float* __restrict__ We1, const float* __restrict__ ae1,
                            const float* __restrict__ We2, const float* __restrict__ ae2,
                            const float* __restrict__ W1, const float* __restrict__ W2,
                            const float* __restrict__ Wc1) {
    int i = blockIdx.x * blockDim.x + threadIdx.x;
    if (i < NN) g_degi[i] = 0;
    if (i == 0) g_rowptr[NN] = EE;
    if (blockIdx.x == 0 && threadIdx.x >= 32 && threadIdx.x < 64) {
        int k = threadIdx.x - 32;
        float s1 = 0.f, s2 = 0.f;
        #pragma unroll 8
        for (int j = 0; j < HH; j++) {
            s1 = fmaf(We1[k * HH + j], ae1[j], s1);
            s2 = fmaf(We2[k * HH + j], ae2[j], s2);
        }
        g_wv1[k] = s1;
        g_wv2[k] = s2;
    }
    // weight pre-pack (first 11264 threads)
    if (i < 4096) {                                   // Wp1: (D0/2)*64
        int k2 = i >> 6, c = i & 63;
        g_Wp1[i] = pk2(W1[(2 * k2) * HH + c], W1[(2 * k2 + 1) * HH + c]);
    } else if (i < 6144) {
        int j = i - 4096, k2 = j >> 6, c = j & 63;
        g_Wp2[j] = pk2(W2[(2 * k2) * HH + c], W2[(2 * k2 + 1) * HH + c]);
    } else if (i < 8192) {
        int j = i - 6144, k2 = j >> 6, c = j & 63;
        g_Wpu[j] = pk2(Wc1[(2 * k2) * HH + c], Wc1[(2 * k2 + 1) * HH + c]);
    } else if (i < 10240) {
        int j = i - 8192, k2 = j >> 6, c = j & 63;
        g_Wpv[j] = pk2(Wc1[(HH + 2 * k2) * HH + c], Wc1[(HH + 2 * k2 + 1) * HH + c]);
    } else if (i < 10240 + DE * 32) {
        int j = i - 10240, k = j >> 5, lane = j & 31;
        const float* p = Wc1 + 2 * HH * HH + k * HH + 2 * lane;
        g_Wpb[j] = pk2(p[0], p[1]);
    }
}

// degree histogram (dst only) + per-edge rank within dst segment
__global__ void __launch_bounds__(256) k_hist(const int* __restrict__ dst) {
    int e = blockIdx.x * 256 + threadIdx.x;   // grid exactly EE/256
    g_rank[e] = atomicAdd(&g_degi[dst[e]], 1);
}

// ---------------- parallel scan: degi -> rowptr ----------------
#define SCAN_B 512
#define SCAN_G 98          // 98*512 = 50176 >= NN

__global__ void __launch_bounds__(SCAN_B) k_scanA() {
    __shared__ int ws[SCAN_B / 32];
    int idx = blockIdx.x * SCAN_B + threadIdx.x;
    int v = (idx < NN) ? g_degi[idx] : 0;
    int s = v;
    #pragma unroll
    for (int o = 16; o > 0; o >>= 1) s += __shfl_xor_sync(0xffffffffu, s, o);
    if ((threadIdx.x & 31) == 0) ws[threadIdx.x >> 5] = s;
    __syncthreads();
    if (threadIdx.x < SCAN_B / 32) {
        int t = ws[threadIdx.x];
        #pragma unroll
        for (int o = 8; o > 0; o >>= 1) t += __shfl_xor_sync(0xffffu, t, o);
        if (threadIdx.x == 0) g_bsum[blockIdx.x] = t;
    }
}

__global__ void __launch_bounds__(SCAN_B) k_scanC() {
    __shared__ int wsum[4];
    __shared__ int ws[SCAN_B / 32];
    __shared__ int spre;
    int tid = threadIdx.x, lane = tid & 31, w = tid >> 5;
    if (tid < 128) {
        int pv = (tid < blockIdx.x) ? g_bsum[tid] : 0;
        #pragma unroll
        for (int o = 16; o > 0; o >>= 1) pv += __shfl_xor_sync(0xffffffffu, pv, o);
        if (lane == 0) wsum[w] = pv;
    }
    int idx = blockIdx.x * SCAN_B + tid;
    int v = (idx < NN) ? g_degi[idx] : 0;
    int inc = v;
    #pragma unroll
    for (int o = 1; o < 32; o <<= 1) {
        int x = __shfl_up_sync(0xffffffffu, inc, o);
        if (lane >= o) inc += x;
    }
    if (lane == 31) ws[w] = inc;
    __syncthreads();
    if (tid == 0) spre = wsum[0] + wsum[1] + wsum[2] + wsum[3];
    if (w == 0 && lane < SCAN_B / 32) {
        int y = ws[lane];
        #pragma unroll
        for (int o = 1; o < SCAN_B / 32; o <<= 1) {
            int x = __shfl_up_sync(0xffffu, y, o);
            if (lane >= o) y += x;
        }
        ws[lane] = y;
    }
    __syncthreads();
    int off = inc - v + (w > 0 ? ws[w - 1] : 0) + spre;
    if (idx < NN) g_rowptr[idx] = off;
}

// fused: compute t1/t2 from ea, scatter packed 16B CSR record (atomic-free via g_rank)
__global__ void __launch_bounds__(256) k_scatter_t(const float* __restrict__ ea,
                                                   const int* __restrict__ src,
                                                   const int* __restrict__ dst) {
    __shared__ float wv1s[DE], wv2s[DE];
    int tid = threadIdx.x;
    if (tid < DE) { wv1s[tid] = g_wv1[tid]; wv2s[tid] = g_wv2[tid]; }
    __syncthreads();
    int e = blockIdx.x * 256 + tid;           // grid exactly EE/256
    const float4* p = (const float4*)(ea + (size_t)e * DE);
    float t1 = 0.f, t2 = 0.f;
    #pragma unroll
    for (int q = 0; q < 8; q++) {
        float4 v = p[q];
        t1 = fmaf(v.x, wv1s[4*q+0], t1); t1 = fmaf(v.y, wv1s[4*q+1], t1);
        t1 = fmaf(v.z, wv1s[4*q+2], t1); t1 = fmaf(v.w, wv1s[4*q+3], t1);
        t2 = fmaf(v.x, wv2s[4*q+0], t2); t2 = fmaf(v.y, wv2s[4*q+1], t2);
        t2 = fmaf(v.z, wv2s[4*q+2], t2); t2 = fmaf(v.w, wv2s[4*q+3], t2);
    }
    int d = dst[e];
    int pos = g_rowptr[d] + g_rank[e];
    g_csr[pos] = make_float4(__int_as_float(src[e]), t1, t2, 0.f);
}

// ---------------- GEMM: 64x64 tile, thread = 4 rows x 4 cols, packed-k FFMA2 ----------------
template <int DIN, int SRC>
__global__ void __launch_bounds__(256, 3) k_gemm(const float* __restrict__ xin_p,
                                                 const ull* __restrict__ Wp_g,
                                                 const float* __restrict__ as,
                                                 const float* __restrict__ ad) {
    extern __shared__ char sm[];
    ull*   Wp = (ull*)sm;                              // (DIN/2) * 64
    float* Xs = (float*)(sm + (DIN / 2) * 64 * 8);     // 64 * DIN
    const float* xin = SRC ? g_x1 : xin_p;
    int tid = threadIdx.x;

    for (int i = tid; i < (DIN / 2) * 64 / 2; i += 256)
        ((ulonglong2*)Wp)[i] = ((const ulonglong2*)Wp_g)[i];
    int r0g = blockIdx.x * 64;                         // grid = ceil(NN/64)
    for (int i = tid; i < 64 * DIN / 4; i += 256) {
        int r = i / (DIN / 4), q = i % (DIN / 4);
        float4 vv = (r0g + r < NN) ? ((const float4*)(xin + (size_t)(r0g + r) * DIN))[q]
                                   : make_float4(0.f, 0.f, 0.f, 0.f);
        ((float4*)Xs)[i] = vv;
    }
    __syncthreads();

    int tx = tid & 15, ty = tid >> 4;                  // cols 4tx..4tx+3, rows 4ty..4ty+3
    const ull* X0 = (const ull*)(Xs + (4 * ty + 0) * DIN);
    const ull* X1 = (const ull*)(Xs + (4 * ty + 1) * DIN);
    const ull* X2 = (const ull*)(Xs + (4 * ty + 2) * DIN);
    const ull* X3 = (const ull*)(Xs + (4 * ty + 3) * DIN);

    ull a00=0,a01=0,a02=0,a03=0, a10=0,a11=0,a12=0,a13=0;
    ull a20=0,a21=0,a22=0,a23=0, a30=0,a31=0,a32=0,a33=0;
    #pragma unroll 8
    for (int k2 = 0; k2 < DIN / 2; k2++) {
        ull x0 = X0[k2], x1 = X1[k2], x2 = X2[k2], x3 = X3[k2];
        ulonglong2 wA = ((const ulonglong2*)(Wp + k2 * 64 + 4 * tx))[0];
        ulonglong2 wB = ((const ulonglong2*)(Wp + k2 * 64 + 4 * tx))[1];
        fma2(a00, x0, wA.x); fma2(a01, x0, wA.y); fma2(a02, x0, wB.x); fma2(a03, x0, wB.y);
        fma2(a10, x1, wA.x); fma2(a11, x1, wA.y); fma2(a12, x1, wB.x); fma2(a13, x1, wB.y);
        fma2(a20, x2, wA.x); fma2(a21, x2, wA.y); fma2(a22, x2, wB.x); fma2(a23, x2, wB.y);
        fma2(a30, x3, wA.x); fma2(a31, x3, wA.y); fma2(a32, x3, wB.x); fma2(a33, x3, wB.y);
    }

    float4 res[4];
    res[0] = make_float4(hsum2(a00), hsum2(a01), hsum2(a02), hsum2(a03));
    res[1] = make_float4(hsum2(a10), hsum2(a11), hsum2(a12), hsum2(a13));
    res[2] = make_float4(hsum2(a20), hsum2(a21), hsum2(a22), hsum2(a23));
    res[3] = make_float4(hsum2(a30), hsum2(a31), hsum2(a32), hsum2(a33));

    float4 as4 = ((const float4*)as)[tx];
    float4 ad4 = ((const float4*)ad)[tx];
    float ps[4], pd[4];
    #pragma unroll
    for (int i = 0; i < 4; i++) {
        int gr = r0g + 4 * ty + i;
        if (gr < NN) ((float4*)(g_h + (size_t)gr * HH))[tx] = res[i];
        ps[i] = res[i].x*as4.x + res[i].y*as4.y + res[i].z*as4.z + res[i].w*as4.w;
        pd[i] = res[i].x*ad4.x + res[i].y*ad4.y + res[i].z*ad4.z + res[i].w*ad4.w;
    }
    #pragma unroll
    for (int o = 8; o > 0; o >>= 1) {
        #pragma unroll
        for (int i = 0; i < 4; i++) {
            ps[i] += __shfl_xor_sync(0xffffffffu, ps[i], o);
            pd[i] += __shfl_xor_sync(0xffffffffu, pd[i], o);
        }
    }
    if (tx == 0) {
        #pragma unroll
        for (int i = 0; i < 4; i++) {
            int gr = r0g + 4 * ty + i;
            if (gr < NN) { g_ssrc[gr] = ps[i]; g_sdst[gr] = pd[i]; }
        }
    }
}

// single-pass per-dst softmax + aggregation, packed CSR records (R5-proven loop)
template <int LAYER>
__global__ void __launch_bounds__(256) k_attn(const float* __restrict__ b) {
    int lane = threadIdx.x & 31;
    int n = blockIdx.x * 8 + (threadIdx.x >> 5);   // grid exactly NN/8
    float* xout = LAYER ? g_x2 : g_x1;
    int beg = g_rowptr[n], end = g_rowptr[n + 1];
    float sd = g_sdst[n], ss = g_ssrc[n];

    const ull* h2 = (const ull*)g_h;
    ull acc2 = 0;
    float ssum = 0.f, tsum = 0.f;
    for (int base = beg; base < end; base += 32) {
        int j = base + lane;
        float ev = 0.f; int si = 0;
        if (j < end) {
            float4 rec = g_csr[j];
            si = __float_as_int(rec.x);
            float t = LAYER ? rec.z : rec.y;
            ev = __expf(lrelu(g_ssrc[si] + sd + t));
            tsum += t;
        }
        ssum += ev;
        int cnt = min(32, end - base);
        #pragma unroll 4
        for (int k = 0; k < cnt; k++) {
            int   s = __shfl_sync(0xffffffffu, si, k);
            float w = __shfl_sync(0xffffffffu, ev, k);
            fma2(acc2, pk2(w, w), h2[(size_t)s * 32 + lane]);
        }
    }
    #pragma unroll
    for (int o = 16; o > 0; o >>= 1) {
        ssum += __shfl_xor_sync(0xffffffffu, ssum, o);
        tsum += __shfl_xor_sync(0xffffffffu, tsum, o);
    }

    float deg = (float)(end - beg);
    float tl = tsum / fmaxf(deg, 1.0f);
    float eself = __expf(lrelu(ss + sd + tl));
    float inv = 1.f / (ssum + eself);
    float aself = eself * inv;

    float2 a = upk2(acc2);
    float2 hn = upk2(h2[(size_t)n * 32 + lane]);
    float2 bv = ((const float2*)b)[lane];
    float2 o2;
    o2.x = fmaxf(fmaf(a.x, inv, fmaf(aself, hn.x, bv.x)), 0.f);
    o2.y = fmaxf(fmaf(a.y, inv, fmaf(aself, hn.y, bv.y)), 0.f);
    ((float2*)xout)[(size_t)n * 32 + lane] = o2;
}

// ---------------- classifier ----------------
// u = x2 @ Wc1[0:64], v = x2 @ Wc1[64:128]  — 64x64 tile, weights copied pre-packed
__global__ void __launch_bounds__(256, 2) k_gemm_uv() {
    __shared__ ull Wu[(HH / 2) * HH];     // 16 KB
    __shared__ ull Wv[(HH / 2) * HH];     // 16 KB
    __shared__ float Xs[64 * HH];         // 16 KB
    int tid = threadIdx.x;
    for (int i = tid; i < (HH / 2) * HH / 2; i += 256) {
        ((ulonglong2*)Wu)[i] = ((const ulonglong2*)g_Wpu)[i];
        ((ulonglong2*)Wv)[i] = ((const ulonglong2*)g_Wpv)[i];
    }
    int r0g = blockIdx.x * 64;                        // grid = ceil(NN/64)
    for (int i = tid; i < 64 * HH / 4; i += 256) {
        int r = i / (HH / 4), q = i % (HH / 4);
        float4 vv = (r0g + r < NN) ? ((const float4*)(g_x2 + (size_t)(r0g + r) * HH))[q]
                                   : make_float4(0.f, 0.f, 0.f, 0.f);
        ((float4*)Xs)[i] = vv;
    }
    __syncthreads();

    int tx = tid & 15, ty = tid >> 4;
    const ull* X0 = (const ull*)(Xs + (4 * ty + 0) * HH);
    const ull* X1 = (const ull*)(Xs + (4 * ty + 1) * HH);
    const ull* X2 = (const ull*)(Xs + (4 * ty + 2) * HH);
    const ull* X3 = (const ull*)(Xs + (4 * ty + 3) * HH);

    ull u00=0,u01=0,u02=0,u03=0, u10=0,u11=0,u12=0,u13=0;
    ull u20=0,u21=0,u22=0,u23=0, u30=0,u31=0,u32=0,u33=0;
    ull v00=0,v01=0,v02=0,v03=0, v10=0,v11=0,v12=0,v13=0;
    ull v20=0,v21=0,v22=0,v23=0, v30=0,v31=0,v32=0,v33=0;
    #pragma unroll 4
    for (int k2 = 0; k2 < HH / 2; k2++) {
        ull x0 = X0[k2], x1 = X1[k2], x2 = X2[k2], x3 = X3[k2];
        ulonglong2 wuA = ((const ulonglong2*)(Wu + k2 * 64 + 4 * tx))[0];
        ulonglong2 wuB = ((const ulonglong2*)(Wu + k2 * 64 + 4 * tx))[1];
        fma2(u00, x0, wuA.x); fma2(u01, x0, wuA.y); fma2(u02, x0, wuB.x); fma2(u03, x0, wuB.y);
        fma2(u10, x1, wuA.x); fma2(u11, x1, wuA.y); fma2(u12, x1, wuB.x); fma2(u13, x1, wuB.y);
        fma2(u20, x2, wuA.x); fma2(u21, x2, wuA.y); fma2(u22, x2, wuB.x); fma2(u23, x2, wuB.y);
        fma2(u30, x3, wuA.x); fma2(u31, x3, wuA.y); fma2(u32, x3, wuB.x); fma2(u33, x3, wuB.y);
        ulonglong2 wvA = ((const ulonglong2*)(Wv + k2 * 64 + 4 * tx))[0];
        ulonglong2 wvB = ((const ulonglong2*)(Wv + k2 * 64 + 4 * tx))[1];
        fma2(v00, x0, wvA.x); fma2(v01, x0, wvA.y); fma2(v02, x0, wvB.x); fma2(v03, x0, wvB.y);
        fma2(v10, x1, wvA.x); fma2(v11, x1, wvA.y); fma2(v12, x1, wvB.x); fma2(v13, x1, wvB.y);
        fma2(v20, x2, wvA.x); fma2(v21, x2, wvA.y); fma2(v22, x2, wvB.x); fma2(v23, x2, wvB.y);
        fma2(v30, x3, wvA.x); fma2(v31, x3, wvA.y); fma2(v32, x3, wvB.x); fma2(v33, x3, wvB.y);
    }

    int gr0 = r0g + 4 * ty;
    if (gr0 + 0 < NN) {
        ((float4*)(g_u + (size_t)(gr0+0) * HH))[tx] = make_float4(hsum2(u00), hsum2(u01), hsum2(u02), hsum2(u03));
        ((float4*)(g_v + (size_t)(gr0+0) * HH))[tx] = make_float4(hsum2(v00), hsum2(v01), hsum2(v02), hsum2(v03));
    }
    if (gr0 + 1 < NN) {
        ((float4*)(g_u + (size_t)(gr0+1) * HH))[tx] = make_float4(hsum2(u10), hsum2(u11), hsum2(u12), hsum2(u13));
        ((float4*)(g_v + (size_t)(gr0+1) * HH))[tx] = make_float4(hsum2(v10), hsum2(v11), hsum2(v12), hsum2(v13));
    }
    if (gr0 + 2 < NN) {
        ((float4*)(g_u + (size_t)(gr0+2) * HH))[tx] = make_float4(hsum2(u20), hsum2(u21), hsum2(u22), hsum2(u23));
        ((float4*)(g_v + (size_t)(gr0+2) * HH))[tx] = make_float4(hsum2(v20), hsum2(v21), hsum2(v22), hsum2(v23));
    }
    if (gr0 + 3 < NN) {
        ((float4*)(g_u + (size_t)(gr0+3) * HH))[tx] = make_float4(hsum2(u30), hsum2(u31), hsum2(u32), hsum2(u33));
        ((float4*)(g_v + (size_t)(gr0+3) * HH))[tx] = make_float4(hsum2(v30), hsum2(v31), hsum2(v32), hsum2(v33));
    }
}

// persistent warp-per-2-edges classifier, f32x2, pipelined gathers (R5-proven loop)
__global__ void __launch_bounds__(256) k_classify(const int* __restrict__ src,
                                                  const int* __restrict__ dst,
                                                  const float* __restrict__ ea,
                                                  const float* __restrict__ bc1,
                                                  const float* __restrict__ Wc2,
                                                  const float* __restrict__ bc2,
                                                  float* __restrict__ out) {
    __shared__ float eas[16][DE];
    int tid = threadIdx.x, lane = tid & 31, w = tid >> 5;

    ull wcol2[DE];
    #pragma unroll
    for (int k = 0; k < DE; k++)
        wcol2[k] = g_Wpb[k * 32 + lane];
    ull  b1v  = ((const ull*)bc1)[lane];
    float2 wc2v = ((const float2*)Wc2)[lane];
    float b2 = bc2[0];

    const ull* u2p = (const ull*)g_u;
    const ull* v2p = (const ull*)g_v;

    for (int eb = blockIdx.x * 16; eb < EE; eb += gridDim.x * 16) {  // EE % 16 == 0
        int e0 = eb + 2 * w, e1 = e0 + 1;
        eas[2*w  ][lane] = ea[(size_t)e0 * DE + lane];
        eas[2*w+1][lane] = ea[(size_t)e1 * DE + lane];
        int s0 = src[e0], d0 = dst[e0], s1 = src[e1], d1 = dst[e1];
        ull Ua = u2p[(size_t)s0 * 32 + lane];
        ull Va = v2p[(size_t)d0 * 32 + lane];
        ull Ub = u2p[(size_t)s1 * 32 + lane];
        ull Vb = v2p[(size_t)d1 * 32 + lane];
        __syncwarp();
        ull acc0 = add2(add2(Ua, Va), b1v);
        ull acc1 = add2(add2(Ub, Vb), b1v);
        #pragma unroll
        for (int k = 0; k < DE; k += 2) {
            float2 ex = *(const float2*)&eas[2*w][k];
            float2 ey = *(const float2*)&eas[2*w+1][k];
            fma2(acc0, pk2(ex.x, ex.x), wcol2[k]);
            fma2(acc0, pk2(ex.y, ex.y), wcol2[k + 1]);
            fma2(acc1, pk2(ey.x, ey.x), wcol2[k]);
            fma2(acc1, pk2(ey.y, ey.y), wcol2[k + 1]);
        }
        float2 a0 = upk2(acc0), a1 = upk2(acc1);
        float r0 = fmaxf(a0.x, 0.f) * wc2v.x + fmaxf(a0.y, 0.f) * wc2v.y;
        float r1 = fmaxf(a1.x, 0.f) * wc2v.x + fmaxf(a1.y, 0.f) * wc2v.y;
        #pragma unroll
        for (int o = 16; o > 0; o >>= 1) {
            r0 += __shfl_xor_sync(0xffffffffu, r0, o);
            r1 += __shfl_xor_sync(0xffffffffu, r1, o);
        }
        if (lane == 0) { out[e0] = r0 + b2; out[e1] = r1 + b2; }
        __syncwarp();
    }
}

// ---------------- host launcher ----------------
extern "C" void kernel_launch(void* const* d_in, const int* in_sizes, int n_in,
                              void* d_out, int out_size) {
    const float* x    = (const float*)d_in[0];
    const int*   ei   = (const int*)  d_in[1];
    const float* ea   = (const float*)d_in[2];
    const float* W1   = (const float*)d_in[3];
    const float* We1  = (const float*)d_in[4];
    const float* as1  = (const float*)d_in[5];
    const float* ad1  = (const float*)d_in[6];
    const float* ae1  = (const float*)d_in[7];
    const float* b1   = (const float*)d_in[8];
    const float* W2   = (const float*)d_in[9];
    const float* We2  = (const float*)d_in[10];
    const float* as2  = (const float*)d_in[11];
    const float* ad2  = (const float*)d_in[12];
    const float* ae2  = (const float*)d_in[13];
    const float* b2   = (const float*)d_in[14];
    const float* Wc1  = (const float*)d_in[15];
    const float* bc1  = (const float*)d_in[16];
    const float* Wc2  = (const float*)d_in[17];
    const float* bc2  = (const float*)d_in[18];
    float*       out  = (float*)d_out;

    const int* src = ei;        // edge_index[0]
    const int* dst = ei + EE;   // edge_index[1]

    const int NB_N = (NN + 255) / 256;       // 196 >= 44 (pack coverage)
    const int NB_E = EE / 256;               // exact
    const int NT64 = (NN + 63) / 64;         // 782
    const int CLS_GRID = 296;                // == resident blocks (2/SM x 148): single wave

    const int SMEM_G1 = (D0 / 2) * 64 * 8 + 64 * D0 * 4;   // 65536
    const int SMEM_G2 = (HH / 2) * 64 * 8 + 64 * HH * 4;   // 32768

    // one-time host resources (created on first, uncaptured, correctness call)
    static cudaStream_t s2 = nullptr;
    static cudaEvent_t evFork = nullptr, evJoin = nullptr;
    if (!s2) {
        cudaFuncSetAttribute(k_gemm<D0, 0>, cudaFuncAttributeMaxDynamicSharedMemorySize, SMEM_G1);
        cudaStreamCreateWithFlags(&s2, cudaStreamNonBlocking);
        cudaEventCreateWithFlags(&evFork, cudaEventDisableTiming);
        cudaEventCreateWithFlags(&evJoin, cudaEventDisableTiming);
    }

    ull* wp1; cudaGetSymbolAddress((void**)&wp1, g_Wp1);
    ull* wp2; cudaGetSymbolAddress((void**)&wp2, g_Wp2);

    // zero+pack first (both sides depend on it)
    k_zero_prep<<<NB_N, 256>>>(We1, ae1, We2, ae2, W1, W2, Wc1);

    // fork: CSR build on s2 concurrently with layer-1 GEMM on the main stream
    cudaEventRecord(evFork, 0);
    cudaStreamWaitEvent(s2, evFork, 0);

    k_hist<<<NB_E, 256, 0, s2>>>(dst);
    k_scanA<<<SCAN_G, SCAN_B, 0, s2>>>();
    k_scanC<<<SCAN_G, SCAN_B, 0, s2>>>();
    k_scatter_t<<<NB_E, 256, 0, s2>>>(ea, src, dst);
    cudaEventRecord(evJoin, s2);

    k_gemm<D0, 0><<<NT64, 256, SMEM_G1>>>(x, wp1, as1, ad1);   // main stream

    cudaStreamWaitEvent(0, evJoin, 0);   // join before attention

    // ---- GAT layer 1 aggregation ----
    k_attn<0><<<NN / 8, 256>>>(b1);

    // ---- GAT layer 2 ----
    k_gemm<HH, 1><<<NT64, 256, SMEM_G2>>>(nullptr, wp2, as2, ad2);
    k_attn<1><<<NN / 8, 256>>>(b2);

    // ---- edge classifier ----
    k_gemm_uv<<<NT64, 256>>>();
    k_classify<<<CLS_GRID, 256>>>(src, dst, ea, bc1, Wc2, bc2, out);
}

// round 15
// speedup vs baseline: 1.2027x; 1.0008x over previous
#include <cuda_runtime.h>

#define NN 50000
#define EE 800000
#define HH 64
#define D0 128
#define DE 32
#define NEG 0.2f

typedef unsigned long long ull;

// ---------------- scratch (static device globals; no allocation) ----------------
__device__ __align__(16) float g_h  [NN * HH];
__device__ __align__(16) float g_x1 [NN * HH];
__device__ __align__(16) float g_x2 [NN * HH];
__device__ __align__(16) float g_u  [NN * HH];
__device__ __align__(16) float g_v  [NN * HH];
__device__ float g_ssrc[NN], g_sdst[NN];
__device__ int   g_degi[NN];
__device__ int   g_rowptr[NN + 1];
__device__ int   g_rank[EE];               // rank of edge within its dst segment
__device__ int   g_bsum[128];
__device__ __align__(16) float4 g_csr[EE]; // {src_bits, t1, t2, pad} per edge, CSR by dst
__device__ float g_wv1[DE], g_wv2[DE];
// pre-packed f32x2 weights (filled once in k_zero_prep)
__device__ __align__(16) ull g_Wp1[(D0 / 2) * HH];   // W1 packed (k-pair, col)
__device__ __align__(16) ull g_Wp2[(HH / 2) * HH];   // W2 packed
__device__ __align__(16) ull g_Wpu[(HH / 2) * HH];   // Wc1[0:64]
__device__ __align__(16) ull g_Wpv[(HH / 2) * HH];   // Wc1[64:128]
__device__ __align__(16) ull g_Wpb[DE * 32];         // Wc1[128:160]: [k][lane] col pair

__device__ __forceinline__ float lrelu(float z) { return z >= 0.f ? z : NEG * z; }

// ---- packed f32x2 helpers ----
__device__ __forceinline__ ull pk2(float x, float y) {
    ull r; asm("mov.b64 %0, {%1,%2};" : "=l"(r) : "f"(x), "f"(y)); return r;
}
__device__ __forceinline__ void fma2(ull& d, ull a, ull b) {
    asm("fma.rn.f32x2 %0, %1, %2, %0;" : "+l"(d) : "l"(a), "l"(b));
}
__device__ __forceinline__ ull add2(ull a, ull b) {
    ull r; asm("add.rn.f32x2 %0, %1, %2;" : "=l"(r) : "l"(a), "l"(b)); return r;
}
__device__ __forceinline__ float2 upk2(ull v) {
    float2 f; asm("mov.b64 {%0,%1}, %2;" : "=f"(f.x), "=f"(f.y) : "l"(v)); return f;
}
__device__ __forceinline__ float hsum2(ull v) {
    float2 f = upk2(v); return f.x + f.y;
}

// ---------------- zero counters + wv = We @ a_edge + weight pre-pack ----------------
__global__ void k_zero_prep(const float* __restrict__ We1, const float* __restrict__ ae1,
                            const float* __restrict__ We2, const float* __restrict__ ae2,
                            const float* __restrict__ W1, const float* __restrict__ W2,
                            const float* __restrict__ Wc1) {
    int i = blockIdx.x * blockDim.x + threadIdx.x;
    if (i < NN) g_degi[i] = 0;
    if (i == 0) g_rowptr[NN] = EE;
    if (blockIdx.x == 0 && threadIdx.x >= 32 && threadIdx.x < 64) {
        int k = threadIdx.x - 32;
        float s1 = 0.f, s2 = 0.f;
        #pragma unroll 8
        for (int j = 0; j < HH; j++) {
            s1 = fmaf(We1[k * HH + j], ae1[j], s1);
            s2 = fmaf(We2[k * HH + j], ae2[j], s2);
        }
        g_wv1[k] = s1;
        g_wv2[k] = s2;
    }
    // weight pre-pack (first 11264 threads)
    if (i < 4096) {                                   // Wp1: (D0/2)*64
        int k2 = i >> 6, c = i & 63;
        g_Wp1[i] = pk2(W1[(2 * k2) * HH + c], W1[(2 * k2 + 1) * HH + c]);
    } else if (i < 6144) {
        int j = i - 4096, k2 = j >> 6, c = j & 63;
        g_Wp2[j] = pk2(W2[(2 * k2) * HH + c], W2[(2 * k2 + 1) * HH + c]);
    } else if (i < 8192) {
        int j = i - 6144, k2 = j >> 6, c = j & 63;
        g_Wpu[j] = pk2(Wc1[(2 * k2) * HH + c], Wc1[(2 * k2 + 1) * HH + c]);
    } else if (i < 10240) {
        int j = i - 8192, k2 = j >> 6, c = j & 63;
        g_Wpv[j] = pk2(Wc1[(HH + 2 * k2) * HH + c], Wc1[(HH + 2 * k2 + 1) * HH + c]);
    } else if (i < 10240 + DE * 32) {
        int j = i - 10240, k = j >> 5, lane = j & 31;
        const float* p = Wc1 + 2 * HH * HH + k * HH + 2 * lane;
        g_Wpb[j] = pk2(p[0], p[1]);
    }
}

// degree histogram (dst only) + per-edge rank within dst segment
__global__ void __launch_bounds__(256) k_hist(const int* __restrict__ dst) {
    int e = blockIdx.x * 256 + threadIdx.x;   // grid exactly EE/256
    g_rank[e] = atomicAdd(&g_degi[dst[e]], 1);
}

// ---------------- parallel scan: degi -> rowptr ----------------
#define SCAN_B 512
#define SCAN_G 98          // 98*512 = 50176 >= NN

__global__ void __launch_bounds__(SCAN_B) k_scanA() {
    __shared__ int ws[SCAN_B / 32];
    int idx = blockIdx.x * SCAN_B + threadIdx.x;
    int v = (idx < NN) ? g_degi[idx] : 0;
    int s = v;
    #pragma unroll
    for (int o = 16; o > 0; o >>= 1) s += __shfl_xor_sync(0xffffffffu, s, o);
    if ((threadIdx.x & 31) == 0) ws[threadIdx.x >> 5] = s;
    __syncthreads();
    if (threadIdx.x < SCAN_B / 32) {
        int t = ws[threadIdx.x];
        #pragma unroll
        for (int o = 8; o > 0; o >>= 1) t += __shfl_xor_sync(0xffffu, t, o);
        if (threadIdx.x == 0) g_bsum[blockIdx.x] = t;
    }
}

__global__ void __launch_bounds__(SCAN_B) k_scanC() {
    __shared__ int wsum[4];
    __shared__ int ws[SCAN_B / 32];
    __shared__ int spre;
    int tid = threadIdx.x, lane = tid & 31, w = tid >> 5;
    if (tid < 128) {
        int pv = (tid < blockIdx.x) ? g_bsum[tid] : 0;
        #pragma unroll
        for (int o = 16; o > 0; o >>= 1) pv += __shfl_xor_sync(0xffffffffu, pv, o);
        if (lane == 0) wsum[w] = pv;
    }
    int idx = blockIdx.x * SCAN_B + tid;
    int v = (idx < NN) ? g_degi[idx] : 0;
    int inc = v;
    #pragma unroll
    for (int o = 1; o < 32; o <<= 1) {
        int x = __shfl_up_sync(0xffffffffu, inc, o);
        if (lane >= o) inc += x;
    }
    if (lane == 31) ws[w] = inc;
    __syncthreads();
    if (tid == 0) spre = wsum[0] + wsum[1] + wsum[2] + wsum[3];
    if (w == 0 && lane < SCAN_B / 32) {
        int y = ws[lane];
        #pragma unroll
        for (int o = 1; o < SCAN_B / 32; o <<= 1) {
            int x = __shfl_up_sync(0xffffu, y, o);
            if (lane >= o) y += x;
        }
        ws[lane] = y;
    }
    __syncthreads();
    int off = inc - v + (w > 0 ? ws[w - 1] : 0) + spre;
    if (idx < NN) g_rowptr[idx] = off;
}

// fused: compute t1/t2 from ea, scatter packed 16B CSR record (atomic-free via g_rank)
__global__ void __launch_bounds__(256) k_scatter_t(const float* __restrict__ ea,
                                                   const int* __restrict__ src,
                                                   const int* __restrict__ dst) {
    __shared__ float wv1s[DE], wv2s[DE];
    int tid = threadIdx.x;
    if (tid < DE) { wv1s[tid] = g_wv1[tid]; wv2s[tid] = g_wv2[tid]; }
    __syncthreads();
    int e = blockIdx.x * 256 + tid;           // grid exactly EE/256
    const float4* p = (const float4*)(ea + (size_t)e * DE);
    float t1 = 0.f, t2 = 0.f;
    #pragma unroll
    for (int q = 0; q < 8; q++) {
        float4 v = p[q];
        t1 = fmaf(v.x, wv1s[4*q+0], t1); t1 = fmaf(v.y, wv1s[4*q+1], t1);
        t1 = fmaf(v.z, wv1s[4*q+2], t1); t1 = fmaf(v.w, wv1s[4*q+3], t1);
        t2 = fmaf(v.x, wv2s[4*q+0], t2); t2 = fmaf(v.y, wv2s[4*q+1], t2);
        t2 = fmaf(v.z, wv2s[4*q+2], t2); t2 = fmaf(v.w, wv2s[4*q+3], t2);
    }
    int d = dst[e];
    int pos = g_rowptr[d] + g_rank[e];
    g_csr[pos] = make_float4(__int_as_float(src[e]), t1, t2, 0.f);
}

// ---------------- GEMM: 64x64 tile, thread = 4 rows x 4 cols, packed-k FFMA2 ----------------
template <int DIN, int SRC>
__global__ void __launch_bounds__(256, 3) k_gemm(const float* __restrict__ xin_p,
                                                 const ull* __restrict__ Wp_g,
                                                 const float* __restrict__ as,
                                                 const float* __restrict__ ad) {
    extern __shared__ char sm[];
    ull*   Wp = (ull*)sm;                              // (DIN/2) * 64
    float* Xs = (float*)(sm + (DIN / 2) * 64 * 8);     // 64 * DIN
    const float* xin = SRC ? g_x1 : xin_p;
    int tid = threadIdx.x;

    for (int i = tid; i < (DIN / 2) * 64 / 2; i += 256)
        ((ulonglong2*)Wp)[i] = ((const ulonglong2*)Wp_g)[i];
    int r0g = blockIdx.x * 64;                         // grid = ceil(NN/64)
    for (int i = tid; i < 64 * DIN / 4; i += 256) {
        int r = i / (DIN / 4), q = i % (DIN / 4);
        float4 vv = (r0g + r < NN) ? ((const float4*)(xin + (size_t)(r0g + r) * DIN))[q]
                                   : make_float4(0.f, 0.f, 0.f, 0.f);
        ((float4*)Xs)[i] = vv;
    }
    __syncthreads();

    int tx = tid & 15, ty = tid >> 4;                  // cols 4tx..4tx+3, rows 4ty..4ty+3
    const ull* X0 = (const ull*)(Xs + (4 * ty + 0) * DIN);
    const ull* X1 = (const ull*)(Xs + (4 * ty + 1) * DIN);
    const ull* X2 = (const ull*)(Xs + (4 * ty + 2) * DIN);
    const ull* X3 = (const ull*)(Xs + (4 * ty + 3) * DIN);

    ull a00=0,a01=0,a02=0,a03=0, a10=0,a11=0,a12=0,a13=0;
    ull a20=0,a21=0,a22=0,a23=0, a30=0,a31=0,a32=0,a33=0;
    #pragma unroll 8
    for (int k2 = 0; k2 < DIN / 2; k2++) {
        ull x0 = X0[k2], x1 = X1[k2], x2 = X2[k2], x3 = X3[k2];
        ulonglong2 wA = ((const ulonglong2*)(Wp + k2 * 64 + 4 * tx))[0];
        ulonglong2 wB = ((const ulonglong2*)(Wp + k2 * 64 + 4 * tx))[1];
        fma2(a00, x0, wA.x); fma2(a01, x0, wA.y); fma2(a02, x0, wB.x); fma2(a03, x0, wB.y);
        fma2(a10, x1, wA.x); fma2(a11, x1, wA.y); fma2(a12, x1, wB.x); fma2(a13, x1, wB.y);
        fma2(a20, x2, wA.x); fma2(a21, x2, wA.y); fma2(a22, x2, wB.x); fma2(a23, x2, wB.y);
        fma2(a30, x3, wA.x); fma2(a31, x3, wA.y); fma2(a32, x3, wB.x); fma2(a33, x3, wB.y);
    }

    float4 res[4];
    res[0] = make_float4(hsum2(a00), hsum2(a01), hsum2(a02), hsum2(a03));
    res[1] = make_float4(hsum2(a10), hsum2(a11), hsum2(a12), hsum2(a13));
    res[2] = make_float4(hsum2(a20), hsum2(a21), hsum2(a22), hsum2(a23));
    res[3] = make_float4(hsum2(a30), hsum2(a31), hsum2(a32), hsum2(a33));

    float4 as4 = ((const float4*)as)[tx];
    float4 ad4 = ((const float4*)ad)[tx];
    float ps[4], pd[4];
    #pragma unroll
    for (int i = 0; i < 4; i++) {
        int gr = r0g + 4 * ty + i;
        if (gr < NN) ((float4*)(g_h + (size_t)gr * HH))[tx] = res[i];
        ps[i] = res[i].x*as4.x + res[i].y*as4.y + res[i].z*as4.z + res[i].w*as4.w;
        pd[i] = res[i].x*ad4.x + res[i].y*ad4.y + res[i].z*ad4.z + res[i].w*ad4.w;
    }
    #pragma unroll
    for (int o = 8; o > 0; o >>= 1) {
        #pragma unroll
        for (int i = 0; i < 4; i++) {
            ps[i] += __shfl_xor_sync(0xffffffffu, ps[i], o);
            pd[i] += __shfl_xor_sync(0xffffffffu, pd[i], o);
        }
    }
    if (tx == 0) {
        #pragma unroll
        for (int i = 0; i < 4; i++) {
            int gr = r0g + 4 * ty + i;
            if (gr < NN) { g_ssrc[gr] = ps[i]; g_sdst[gr] = pd[i]; }
        }
    }
}

// single-pass per-dst softmax + aggregation, packed CSR records (R5-proven loop)
template <int LAYER>
__global__ void __launch_bounds__(256) k_attn(const float* __restrict__ b) {
    int lane = threadIdx.x & 31;
    int n = blockIdx.x * 8 + (threadIdx.x >> 5);   // grid exactly NN/8
    float* xout = LAYER ? g_x2 : g_x1;
    int beg = g_rowptr[n], end = g_rowptr[n + 1];
    float sd = g_sdst[n], ss = g_ssrc[n];

    const ull* h2 = (const ull*)g_h;
    ull acc2 = 0;
    float ssum = 0.f, tsum = 0.f;
    for (int base = beg; base < end; base += 32) {
        int j = base + lane;
        float ev = 0.f; int si = 0;
        if (j < end) {
            float4 rec = g_csr[j];
            si = __float_as_int(rec.x);
            float t = LAYER ? rec.z : rec.y;
            ev = __expf(lrelu(g_ssrc[si] + sd + t));
            tsum += t;
        }
        ssum += ev;
        int cnt = min(32, end - base);
        #pragma unroll 4
        for (int k = 0; k < cnt; k++) {
            int   s = __shfl_sync(0xffffffffu, si, k);
            float w = __shfl_sync(0xffffffffu, ev, k);
            fma2(acc2, pk2(w, w), h2[(size_t)s * 32 + lane]);
        }
    }
    #pragma unroll
    for (int o = 16; o > 0; o >>= 1) {
        ssum += __shfl_xor_sync(0xffffffffu, ssum, o);
        tsum += __shfl_xor_sync(0xffffffffu, tsum, o);
    }

    float deg = (float)(end - beg);
    float tl = tsum / fmaxf(deg, 1.0f);
    float eself = __expf(lrelu(ss + sd + tl));
    float inv = 1.f / (ssum + eself);
    float aself = eself * inv;

    float2 a = upk2(acc2);
    float2 hn = upk2(h2[(size_t)n * 32 + lane]);
    float2 bv = ((const float2*)b)[lane];
    float2 o2;
    o2.x = fmaxf(fmaf(a.x, inv, fmaf(aself, hn.x, bv.x)), 0.f);
    o2.y = fmaxf(fmaf(a.y, inv, fmaf(aself, hn.y, bv.y)), 0.f);
    ((float2*)xout)[(size_t)n * 32 + lane] = o2;
}

// ---------------- classifier ----------------
// u = x2 @ Wc1[0:64], v = x2 @ Wc1[64:128]  — 64x64 tile, weights copied pre-packed
__global__ void __launch_bounds__(256, 2) k_gemm_uv() {
    __shared__ ull Wu[(HH / 2) * HH];     // 16 KB
    __shared__ ull Wv[(HH / 2) * HH];     // 16 KB
    __shared__ float Xs[64 * HH];         // 16 KB
    int tid = threadIdx.x;
    for (int i = tid; i < (HH / 2) * HH / 2; i += 256) {
        ((ulonglong2*)Wu)[i] = ((const ulonglong2*)g_Wpu)[i];
        ((ulonglong2*)Wv)[i] = ((const ulonglong2*)g_Wpv)[i];
    }
    int r0g = blockIdx.x * 64;                        // grid = ceil(NN/64)
    for (int i = tid; i < 64 * HH / 4; i += 256) {
        int r = i / (HH / 4), q = i % (HH / 4);
        float4 vv = (r0g + r < NN) ? ((const float4*)(g_x2 + (size_t)(r0g + r) * HH))[q]
                                   : make_float4(0.f, 0.f, 0.f, 0.f);
        ((float4*)Xs)[i] = vv;
    }
    __syncthreads();

    int tx = tid & 15, ty = tid >> 4;
    const ull* X0 = (const ull*)(Xs + (4 * ty + 0) * HH);
    const ull* X1 = (const ull*)(Xs + (4 * ty + 1) * HH);
    const ull* X2 = (const ull*)(Xs + (4 * ty + 2) * HH);
    const ull* X3 = (const ull*)(Xs + (4 * ty + 3) * HH);

    ull u00=0,u01=0,u02=0,u03=0, u10=0,u11=0,u12=0,u13=0;
    ull u20=0,u21=0,u22=0,u23=0, u30=0,u31=0,u32=0,u33=0;
    ull v00=0,v01=0,v02=0,v03=0, v10=0,v11=0,v12=0,v13=0;
    ull v20=0,v21=0,v22=0,v23=0, v30=0,v31=0,v32=0,v33=0;
    #pragma unroll 4
    for (int k2 = 0; k2 < HH / 2; k2++) {
        ull x0 = X0[k2], x1 = X1[k2], x2 = X2[k2], x3 = X3[k2];
        ulonglong2 wuA = ((const ulonglong2*)(Wu + k2 * 64 + 4 * tx))[0];
        ulonglong2 wuB = ((const ulonglong2*)(Wu + k2 * 64 + 4 * tx))[1];
        fma2(u00, x0, wuA.x); fma2(u01, x0, wuA.y); fma2(u02, x0, wuB.x); fma2(u03, x0, wuB.y);
        fma2(u10, x1, wuA.x); fma2(u11, x1, wuA.y); fma2(u12, x1, wuB.x); fma2(u13, x1, wuB.y);
        fma2(u20, x2, wuA.x); fma2(u21, x2, wuA.y); fma2(u22, x2, wuB.x); fma2(u23, x2, wuB.y);
        fma2(u30, x3, wuA.x); fma2(u31, x3, wuA.y); fma2(u32, x3, wuB.x); fma2(u33, x3, wuB.y);
        ulonglong2 wvA = ((const ulonglong2*)(Wv + k2 * 64 + 4 * tx))[0];
        ulonglong2 wvB = ((const ulonglong2*)(Wv + k2 * 64 + 4 * tx))[1];
        fma2(v00, x0, wvA.x); fma2(v01, x0, wvA.y); fma2(v02, x0, wvB.x); fma2(v03, x0, wvB.y);
        fma2(v10, x1, wvA.x); fma2(v11, x1, wvA.y); fma2(v12, x1, wvB.x); fma2(v13, x1, wvB.y);
        fma2(v20, x2, wvA.x); fma2(v21, x2, wvA.y); fma2(v22, x2, wvB.x); fma2(v23, x2, wvB.y);
        fma2(v30, x3, wvA.x); fma2(v31, x3, wvA.y); fma2(v32, x3, wvB.x); fma2(v33, x3, wvB.y);
    }

    int gr0 = r0g + 4 * ty;
    if (gr0 + 0 < NN) {
        ((float4*)(g_u + (size_t)(gr0+0) * HH))[tx] = make_float4(hsum2(u00), hsum2(u01), hsum2(u02), hsum2(u03));
        ((float4*)(g_v + (size_t)(gr0+0) * HH))[tx] = make_float4(hsum2(v00), hsum2(v01), hsum2(v02), hsum2(v03));
    }
    if (gr0 + 1 < NN) {
        ((float4*)(g_u + (size_t)(gr0+1) * HH))[tx] = make_float4(hsum2(u10), hsum2(u11), hsum2(u12), hsum2(u13));
        ((float4*)(g_v + (size_t)(gr0+1) * HH))[tx] = make_float4(hsum2(v10), hsum2(v11), hsum2(v12), hsum2(v13));
    }
    if (gr0 + 2 < NN) {
        ((float4*)(g_u + (size_t)(gr0+2) * HH))[tx] = make_float4(hsum2(u20), hsum2(u21), hsum2(u22), hsum2(u23));
        ((float4*)(g_v + (size_t)(gr0+2) * HH))[tx] = make_float4(hsum2(v20), hsum2(v21), hsum2(v22), hsum2(v23));
    }
    if (gr0 + 3 < NN) {
        ((float4*)(g_u + (size_t)(gr0+3) * HH))[tx] = make_float4(hsum2(u30), hsum2(u31), hsum2(u32), hsum2(u33));
        ((float4*)(g_v + (size_t)(gr0+3) * HH))[tx] = make_float4(hsum2(v30), hsum2(v31), hsum2(v32), hsum2(v33));
    }
}

// persistent warp-per-2-edges classifier; weight cache in SMEM (frees ~60 regs
// -> 4+ blocks/SM, doubled latency hiding). Gather/math loop structure unchanged.
__global__ void __launch_bounds__(256, 4) k_classify(const int* __restrict__ src,
                                                     const int* __restrict__ dst,
                                                     const float* __restrict__ ea,
                                                     const float* __restrict__ bc1,
                                                     const float* __restrict__ Wc2,
                                                     const float* __restrict__ bc2,
                                                     float* __restrict__ out) {
    __shared__ __align__(16) ull wsm[DE * 32];   // 8 KB: [k][lane] packed col pair
    __shared__ float eas[16][DE];
    int tid = threadIdx.x, lane = tid & 31, w = tid >> 5;

    for (int i = tid; i < DE * 32; i += 256) wsm[i] = g_Wpb[i];
    __syncthreads();

    ull  b1v  = ((const ull*)bc1)[lane];
    float2 wc2v = ((const float2*)Wc2)[lane];
    float b2 = bc2[0];

    const ull* u2p = (const ull*)g_u;
    const ull* v2p = (const ull*)g_v;

    for (int eb = blockIdx.x * 16; eb < EE; eb += gridDim.x * 16) {  // EE % 16 == 0
        int e0 = eb + 2 * w, e1 = e0 + 1;
        eas[2*w  ][lane] = ea[(size_t)e0 * DE + lane];
        eas[2*w+1][lane] = ea[(size_t)e1 * DE + lane];
        int s0 = src[e0], d0 = dst[e0], s1 = src[e1], d1 = dst[e1];
        ull Ua = u2p[(size_t)s0 * 32 + lane];
        ull Va = v2p[(size_t)d0 * 32 + lane];
        ull Ub = u2p[(size_t)s1 * 32 + lane];
        ull Vb = v2p[(size_t)d1 * 32 + lane];
        __syncwarp();
        ull acc0 = add2(add2(Ua, Va), b1v);
        ull acc1 = add2(add2(Ub, Vb), b1v);
        #pragma unroll
        for (int k = 0; k < DE; k += 2) {
            ull wk0 = wsm[k * 32 + lane];
            ull wk1 = wsm[(k + 1) * 32 + lane];
            float2 ex = *(const float2*)&eas[2*w][k];
            float2 ey = *(const float2*)&eas[2*w+1][k];
            fma2(acc0, pk2(ex.x, ex.x), wk0);
            fma2(acc0, pk2(ex.y, ex.y), wk1);
            fma2(acc1, pk2(ey.x, ey.x), wk0);
            fma2(acc1, pk2(ey.y, ey.y), wk1);
        }
        float2 a0 = upk2(acc0), a1 = upk2(acc1);
        float r0 = fmaxf(a0.x, 0.f) * wc2v.x + fmaxf(a0.y, 0.f) * wc2v.y;
        float r1 = fmaxf(a1.x, 0.f) * wc2v.x + fmaxf(a1.y, 0.f) * wc2v.y;
        #pragma unroll
        for (int o = 16; o > 0; o >>= 1) {
            r0 += __shfl_xor_sync(0xffffffffu, r0, o);
            r1 += __shfl_xor_sync(0xffffffffu, r1, o);
        }
        if (lane == 0) { out[e0] = r0 + b2; out[e1] = r1 + b2; }
        __syncwarp();
    }
}

// ---------------- host launcher ----------------
extern "C" void kernel_launch(void* const* d_in, const int* in_sizes, int n_in,
                              void* d_out, int out_size) {
    const float* x    = (const float*)d_in[0];
    const int*   ei   = (const int*)  d_in[1];
    const float* ea   = (const float*)d_in[2];
    const float* W1   = (const float*)d_in[3];
    const float* We1  = (const float*)d_in[4];
    const float* as1  = (const float*)d_in[5];
    const float* ad1  = (const float*)d_in[6];
    const float* ae1  = (const float*)d_in[7];
    const float* b1   = (const float*)d_in[8];
    const float* W2   = (const float*)d_in[9];
    const float* We2  = (const float*)d_in[10];
    const float* as2  = (const float*)d_in[11];
    const float* ad2  = (const float*)d_in[12];
    const float* ae2  = (const float*)d_in[13];
    const float* b2   = (const float*)d_in[14];
    const float* Wc1  = (const float*)d_in[15];
    const float* bc1  = (const float*)d_in[16];
    const float* Wc2  = (const float*)d_in[17];
    const float* bc2  = (const float*)d_in[18];
    float*       out  = (float*)d_out;

    const int* src = ei;        // edge_index[0]
    const int* dst = ei + EE;   // edge_index[1]

    const int NB_N = (NN + 255) / 256;       // 196 >= 44 (pack coverage)
    const int NB_E = EE / 256;               // exact
    const int NT64 = (NN + 63) / 64;         // 782
    const int CLS_GRID = 592;                // == guaranteed resident (4/SM x 148): single wave

    const int SMEM_G1 = (D0 / 2) * 64 * 8 + 64 * D0 * 4;   // 65536
    const int SMEM_G2 = (HH / 2) * 64 * 8 + 64 * HH * 4;   // 32768

    // one-time host resources (created on first, uncaptured, correctness call)
    static cudaStream_t s2 = nullptr;
    static cudaEvent_t evFork = nullptr, evJoin = nullptr;
    if (!s2) {
        cudaFuncSetAttribute(k_gemm<D0, 0>, cudaFuncAttributeMaxDynamicSharedMemorySize, SMEM_G1);
        cudaStreamCreateWithFlags(&s2, cudaStreamNonBlocking);
        cudaEventCreateWithFlags(&evFork, cudaEventDisableTiming);
        cudaEventCreateWithFlags(&evJoin, cudaEventDisableTiming);
    }

    ull* wp1; cudaGetSymbolAddress((void**)&wp1, g_Wp1);
    ull* wp2; cudaGetSymbolAddress((void**)&wp2, g_Wp2);

    // zero+pack first (both sides depend on it)
    k_zero_prep<<<NB_N, 256>>>(We1, ae1, We2, ae2, W1, W2, Wc1);

    // fork: CSR build on s2 concurrently with layer-1 GEMM on the main stream
    cudaEventRecord(evFork, 0);
    cudaStreamWaitEvent(s2, evFork, 0);

    k_hist<<<NB_E, 256, 0, s2>>>(dst);
    k_scanA<<<SCAN_G, SCAN_B, 0, s2>>>();
    k_scanC<<<SCAN_G, SCAN_B, 0, s2>>>();
    k_scatter_t<<<NB_E, 256, 0, s2>>>(ea, src, dst);
    cudaEventRecord(evJoin, s2);

    k_gemm<D0, 0><<<NT64, 256, SMEM_G1>>>(x, wp1, as1, ad1);   // main stream

    cudaStreamWaitEvent(0, evJoin, 0);   // join before attention

    // ---- GAT layer 1 aggregation ----
    k_attn<0><<<NN / 8, 256>>>(b1);

    // ---- GAT layer 2 ----
    k_gemm<HH, 1><<<NT64, 256, SMEM_G2>>>(nullptr, wp2, as2, ad2);
    k_attn<1><<<NN / 8, 256>>>(b2);

    // ---- edge classifier ----
    k_gemm_uv<<<NT64, 256>>>();
    k_classify<<<CLS_GRID, 256>>>(src, dst, ea, bc1, Wc2, bc2, out);
}